// round 8
// baseline (speedup 1.0000x reference)
#include <cuda_runtime.h>
#include <math.h>

#define SVOL 64000
#define BB   2
#define CC   96
#define NHD  4
#define HD   24
#define LAX  40

typedef unsigned long long ull;

// ---- scratch: __device__ globals (no allocation anywhere) ----
__device__ float g_buf0[BB*CC*SVOL];   // conv out t1 -> x*mod
__device__ float g_buf1[BB*CC*SVOL];   // u -> attention accumulator
__device__ float g_qkv [BB*288*SVOL];
__device__ float g_pad [(size_t)BB*96*42*42*44];   // circularly padded pos_emb
__device__ float g_mu1[BB*CC], g_rs1[BB*CC], g_mu2[BB*CC], g_rs2[BB*CC];
__device__ float g_W27  [27*96*96];
__device__ float g_WcT  [96*96];
__device__ float g_bc   [96];
__device__ float g_mod2T[96*96];
__device__ float g_qkvT [96*288];
__device__ float g_projT[96*96];

__device__ __forceinline__ float gelu_f(float v){
    return 0.5f*v*(1.0f + erff(v*0.70710678118654752f));
}
__device__ __forceinline__ ull pack_dup(float x){
    ull r; asm("mov.b64 %0, {%1, %1};" : "=l"(r) : "f"(x)); return r;
}
__device__ __forceinline__ void fma2(ull& d, ull a, ull b){
    asm("fma.rn.f32x2 %0, %1, %2, %0;" : "+l"(d) : "l"(a), "l"(b));
}
__device__ __forceinline__ void unpack2(float& lo, float& hi, ull v){
    asm("mov.b64 {%0, %1}, %2;" : "=f"(lo), "=f"(hi) : "l"(v));
}

// ---- weight / input prep ----
__global__ void prep_w27(const float* __restrict__ lp1_w){
    int tid = blockIdx.x*blockDim.x + threadIdx.x;
    if (tid < 27*96*96){
        int t = tid/(96*96); int r = tid%(96*96); int ic = r/96; int oc = r%96;
        g_W27[tid] = lp1_w[(oc*96+ic)*27 + t];
    }
}
__global__ void prep_pad(const float* __restrict__ pe){
    size_t idx = (size_t)blockIdx.x*256 + threadIdx.x;
    if (idx >= (size_t)BB*96*42*42*44) return;
    int pw = (int)(idx % 44); size_t r = idx/44;
    int ph = (int)(r % 42); r /= 42;
    int pd = (int)(r % 42); r /= 42;
    int c  = (int)(r % 96); int b = (int)(r/96);
    int d = (pd+39)%40, h = (ph+39)%40, w = (pw+39)%40;
    g_pad[idx] = pe[(size_t)(b*96+c)*SVOL + d*1600 + h*40 + w];
}
__global__ void prep_fold(const float* __restrict__ mod1_w, const float* __restrict__ lp2_w,
                          const float* __restrict__ lp2_b, const float* __restrict__ mod1_b){
    int tid = blockIdx.x*blockDim.x + threadIdx.x;
    if (tid < 96*96){
        int k = tid/96, m = tid%96;
        float s = 0.f;
        for (int o = 0; o < 96; o++) s += mod1_w[m*96+o]*lp2_w[o*96+k];
        g_WcT[k*96+m] = s;
        if (k == 0){
            float b2 = 0.f;
            for (int o = 0; o < 96; o++) b2 += mod1_w[m*96+o]*lp2_b[o];
            g_bc[m] = b2 + mod1_b[m];
        }
    }
}
__global__ void prep_trans(const float* __restrict__ mod2_w, const float* __restrict__ qkv_w,
                           const float* __restrict__ proj_w){
    int tid = blockIdx.x*blockDim.x + threadIdx.x;
    if (tid < 96*96){
        int k = tid/96, m = tid%96;
        g_mod2T[k*96+m] = mod2_w[m*96+k];
        g_projT[k*96+m] = proj_w[m*96+k];
    }
    if (tid < 96*288){
        int k = tid/288, m = tid%288;
        g_qkvT[k*288+m] = qkv_w[m*96+k];
    }
}

// ---- conv3x3x3 circular, f32x2 packed over oc pairs, padded input ----
// smem: Xs[16 ic][4 rows][44] = 11.3KB, Ws3[3 dx][16 ic][96 oc] = 18.4KB
__global__ __launch_bounds__(96) void conv3_kernel(const float* __restrict__ lp1_b){
    __shared__ float Xs [16*4*44];
    __shared__ float Ws3[3*16*96];
    int b = blockIdx.z, d = blockIdx.y, h0 = blockIdx.x*2;
    int tid = threadIdx.x;
    int tm = tid/8, tn = tid%8;       // tm: oc-octet 0..11, tn: col group 0..7
    int cb = tn*10;
    int g  = cb/40;                   // output row within 2-row tile
    int wb = cb%40;

    ull acc2[4][10];
    #pragma unroll
    for (int i=0;i<4;i++)
        #pragma unroll
        for (int j=0;j<10;j++) acc2[i][j] = 0ULL;

    for (int dz=0; dz<3; dz++){
        int pd = d + dz;              // padded depth index
        for (int kc=0; kc<6; kc++){
            __syncthreads();
            // stage Xs: 64 rows (16 ic x 4 padded h-rows) x 11 float4, contiguous
            for (int idx=tid; idx<704; idx+=96){
                int row = idx/11, q = idx - row*11;
                int ic = row>>2, rr = row&3;
                size_t src = (((size_t)(b*96 + kc*16 + ic)*42 + pd)*42 + (h0+rr))*44 + q*4;
                *reinterpret_cast<float4*>(&Xs[(ic*4+rr)*44 + q*4]) =
                    *reinterpret_cast<const float4*>(&g_pad[src]);
            }
            for (int dy=0; dy<3; dy++){
                int t0 = (dz*3+dy)*3;
                __syncthreads();
                for (int idx=tid; idx<1152; idx+=96){
                    int dx = idx/384, rr = idx - dx*384;
                    *reinterpret_cast<float4*>(&Ws3[dx*1536 + rr*4]) =
                        *reinterpret_cast<const float4*>(&g_W27[(size_t)(t0+dx)*9216 + kc*16*96 + rr*4]);
                }
                __syncthreads();
                for (int k=0;k<16;k++){
                    ull xp[12];
                    #pragma unroll
                    for (int l=0;l<12;l++)
                        xp[l] = pack_dup(Xs[(k*4 + g + dy)*44 + wb + l]);
                    #pragma unroll
                    for (int dx=0;dx<3;dx++){
                        const ull* wp = reinterpret_cast<const ull*>(&Ws3[dx*1536 + k*96 + tm*8]);
                        ull w2[4];
                        #pragma unroll
                        for (int i=0;i<4;i++) w2[i] = wp[i];
                        #pragma unroll
                        for (int i=0;i<4;i++)
                            #pragma unroll
                            for (int j=0;j<10;j++)
                                fma2(acc2[i][j], w2[i], xp[j+dx]);
                    }
                }
            }
        }
    }
    size_t obase = (size_t)b*CC*SVOL + d*1600 + (h0+g)*40 + wb;
    #pragma unroll
    for (int i=0;i<4;i++){
        int oc0 = tm*8 + 2*i;
        float b0 = lp1_b[oc0], b1 = lp1_b[oc0+1];
        #pragma unroll
        for (int j=0;j<10;j++){
            float lo, hi; unpack2(lo, hi, acc2[i][j]);
            g_buf0[obase + (size_t)oc0*SVOL + j]     = lo + b0;
            g_buf0[obase + (size_t)(oc0+1)*SVOL + j] = hi + b1;
        }
    }
}

// ---- per-(b,c) instance-norm stats ----
template<int SRC, int SET>
__global__ __launch_bounds__(256) void in_stats(){
    const float* src = (SRC==0) ? g_buf0 : g_buf1;
    float* mu = (SET==1) ? g_mu1 : g_mu2;
    float* rs = (SET==1) ? g_rs1 : g_rs2;
    int bc = blockIdx.x;
    const float* p = src + (size_t)bc*SVOL;
    float s=0.f, s2=0.f;
    for (int i=threadIdx.x; i<SVOL/4; i+=256){
        float4 v = reinterpret_cast<const float4*>(p)[i];
        s += v.x+v.y+v.z+v.w;
        s2 = fmaf(v.x,v.x,s2); s2 = fmaf(v.y,v.y,s2);
        s2 = fmaf(v.z,v.z,s2); s2 = fmaf(v.w,v.w,s2);
    }
    __shared__ float r1[256], r2[256];
    r1[threadIdx.x]=s; r2[threadIdx.x]=s2;
    __syncthreads();
    for (int off=128; off>0; off>>=1){
        if (threadIdx.x<off){ r1[threadIdx.x]+=r1[threadIdx.x+off]; r2[threadIdx.x]+=r2[threadIdx.x+off]; }
        __syncthreads();
    }
    if (threadIdx.x==0){
        float m = r1[0]*(1.0f/SVOL);
        float var = r2[0]*(1.0f/SVOL) - m*m;
        mu[bc]=m; rs[bc]=rsqrtf(var + 1e-5f);
    }
}

// ---- fused 1x1-conv GEMM, f32x2 packed over m pairs ----
template<int PRO, int EPI, int AW, int SRC, int DST, int SET, int BIASG>
__global__ __launch_bounds__(192) void gemm_kernel(
    int Mtotal, float* __restrict__ extY,
    const float* __restrict__ bias_ext,
    const float* __restrict__ gate)
{
    __shared__ float As[48*96];
    __shared__ float Xs[48*128];
    const float* AT = (AW==0) ? g_WcT : (AW==1) ? g_mod2T : (AW==2) ? g_qkvT : g_projT;
    const float* X  = (SRC==0) ? g_buf0 : g_buf1;
    float* Y = (DST==0) ? g_buf0 : (DST==1) ? g_buf1 : (DST==2) ? g_qkv : extY;
    const float* bias = (BIASG==1) ? g_bc : bias_ext;
    const float* mu = (SET==1) ? g_mu1 : g_mu2;
    const float* rs = (SET==1) ? g_rs1 : g_rs2;

    int b = blockIdx.z, m0 = blockIdx.y*96, n0 = blockIdx.x*128;
    int tid = threadIdx.x, tm = tid/16, tn = tid%16;   // 12 x 16
    const float* xb = X + (size_t)b*96*SVOL + n0;

    ull acc2[4][8];
    #pragma unroll
    for (int i=0;i<4;i++)
        #pragma unroll
        for (int j=0;j<8;j++) acc2[i][j]=0ULL;

    for (int kc=0; kc<2; kc++){
        __syncthreads();
        for (int idx=tid; idx<1152; idx+=192){
            int k = idx/24, mq = idx%24;
            *reinterpret_cast<float4*>(&As[k*96 + mq*4]) =
                *reinterpret_cast<const float4*>(&AT[(kc*48+k)*Mtotal + m0 + mq*4]);
        }
        for (int idx=tid; idx<1536; idx+=192){
            int k = idx/32, cq = idx%32;
            int kg = kc*48 + k;
            float4 v = *reinterpret_cast<const float4*>(&xb[(size_t)kg*SVOL + cq*4]);
            if (PRO==1){
                float m = mu[b*96+kg], r = rs[b*96+kg];
                v.x = gelu_f((v.x-m)*r); v.y = gelu_f((v.y-m)*r);
                v.z = gelu_f((v.z-m)*r); v.w = gelu_f((v.w-m)*r);
            }
            *reinterpret_cast<float4*>(&Xs[k*128 + cq*4]) = v;
        }
        __syncthreads();
        for (int k=0;k<48;k++){
            const ull* wp = reinterpret_cast<const ull*>(&As[k*96 + tm*8]);
            ull w2[4];
            #pragma unroll
            for (int i=0;i<4;i++) w2[i] = wp[i];
            float4 x0 = *reinterpret_cast<const float4*>(&Xs[k*128 + tn*8]);
            float4 x1 = *reinterpret_cast<const float4*>(&Xs[k*128 + tn*8 + 4]);
            ull xp[8] = { pack_dup(x0.x), pack_dup(x0.y), pack_dup(x0.z), pack_dup(x0.w),
                          pack_dup(x1.x), pack_dup(x1.y), pack_dup(x1.z), pack_dup(x1.w) };
            #pragma unroll
            for (int i=0;i<4;i++)
                #pragma unroll
                for (int j=0;j<8;j++) fma2(acc2[i][j], w2[i], xp[j]);
        }
    }

    #pragma unroll
    for (int i=0;i<4;i++){
        int m = m0 + tm*8 + 2*i;
        float bi0 = bias[m], bi1 = bias[m+1];
        #pragma unroll
        for (int j=0;j<8;j++){
            int col = n0 + tn*8 + j;
            float lo, hi; unpack2(lo, hi, acc2[i][j]);
            float r0 = lo + bi0, r1 = hi + bi1;
            if (EPI==1){
                float g0 = gate[((size_t)b*96 + m  )*SVOL + col];
                float g1 = gate[((size_t)b*96 + m+1)*SVOL + col];
                r0 = g0 * (1.0f/(1.0f + __expf(-r0)));
                r1 = g1 * (1.0f/(1.0f + __expf(-r1)));
            }
            Y[((size_t)b*Mtotal + m  )*SVOL + col] = r0;
            Y[((size_t)b*Mtotal + m+1)*SVOL + col] = r1;
        }
    }
}

// ---- axial attention (rotation + pos_attn mathematically eliminated); out -> g_buf1 ----
template<int AXIS, bool ACCUM>
__global__ __launch_bounds__(128) void attn_kernel(){
    __shared__ float qs[HD][LAX];
    __shared__ float ks[HD][LAX];
    __shared__ float vs[LAX][HD];
    __shared__ float ps[LAX][LAX];
    int line = blockIdx.x, head = blockIdx.y, b = blockIdx.z;
    int tid = threadIdx.x;
    int s0 = 0, stride = 1;
    if (AXIS==0){ int d=line/40, h=line%40; s0 = d*1600 + h*40; stride = 1;    }
    if (AXIS==1){ int d=line/40, w=line%40; s0 = d*1600 + w;    stride = 40;   }
    if (AXIS==2){ int h=line/40, w=line%40; s0 = h*40 + w;      stride = 1600; }
    const float* base = g_qkv + (size_t)b*288*SVOL;

    for (int idx=tid; idx<2*HD*LAX; idx+=128){
        int t = idx/960, r = idx%960, hd = r/40, l = r%40;
        float v = base[(size_t)((t*NHD+head)*HD + hd)*SVOL + s0 + l*stride];
        if (t==0) qs[hd][l]=v; else ks[hd][l]=v;
    }
    for (int idx=tid; idx<HD*LAX; idx+=128){
        int hd = idx/40, l = idx%40;
        vs[l][hd] = base[(size_t)((2*NHD+head)*HD + hd)*SVOL + s0 + l*stride];
    }
    __syncthreads();

    const float scale = 0.2041241452319315f;  // 24^-0.5
    for (int idx=tid; idx<400; idx+=128){
        int i = idx/10, j0 = (idx%10)*4;
        float a0=0.f,a1=0.f,a2=0.f,a3=0.f;
        #pragma unroll
        for (int hd=0; hd<HD; hd++){
            float qv = qs[hd][i];
            float4 kv = *reinterpret_cast<const float4*>(&ks[hd][j0]);
            a0 = fmaf(qv,kv.x,a0); a1 = fmaf(qv,kv.y,a1);
            a2 = fmaf(qv,kv.z,a2); a3 = fmaf(qv,kv.w,a3);
        }
        ps[i][j0+0]=a0*scale; ps[i][j0+1]=a1*scale;
        ps[i][j0+2]=a2*scale; ps[i][j0+3]=a3*scale;
    }
    __syncthreads();
    if (tid < 40){
        float mx = -1e30f;
        for (int j=0;j<40;j++) mx = fmaxf(mx, ps[tid][j]);
        float sum = 0.f;
        for (int j=0;j<40;j++){ float e = __expf(ps[tid][j]-mx); ps[tid][j]=e; sum+=e; }
        float inv = 1.0f/sum;
        for (int j=0;j<40;j++) ps[tid][j]*=inv;
    }
    __syncthreads();
    for (int idx=tid; idx<240; idx+=128){
        int i = idx/6, hd0 = (idx%6)*4;
        float a0=0.f,a1=0.f,a2=0.f,a3=0.f;
        #pragma unroll
        for (int j=0;j<40;j++){
            float pv = ps[i][j];
            float4 vv = *reinterpret_cast<const float4*>(&vs[j][hd0]);
            a0 = fmaf(pv,vv.x,a0); a1 = fmaf(pv,vv.y,a1);
            a2 = fmaf(pv,vv.z,a2); a3 = fmaf(pv,vv.w,a3);
        }
        float r[4] = {a0,a1,a2,a3};
        #pragma unroll
        for (int q=0;q<4;q++){
            size_t oi = ((size_t)b*CC + head*HD + hd0 + q)*SVOL + s0 + i*stride;
            if (ACCUM) g_buf1[oi] += r[q]; else g_buf1[oi] = r[q];
        }
    }
}

extern "C" void kernel_launch(void* const* d_in, const int* in_sizes, int n_in,
                              void* d_out, int out_size){
    const float* x     = (const float*)d_in[0];
    const float* pe    = (const float*)d_in[1];
    const float* qkv_w = (const float*)d_in[2];
    const float* qkv_b = (const float*)d_in[3];
    const float* lp1_w = (const float*)d_in[4];
    const float* lp1_b = (const float*)d_in[5];
    const float* lp2_w = (const float*)d_in[6];
    const float* lp2_b = (const float*)d_in[7];
    const float* mod1_w= (const float*)d_in[8];
    const float* mod1_b= (const float*)d_in[9];
    const float* mod2_w= (const float*)d_in[10];
    const float* mod2_b= (const float*)d_in[11];
    // d_in[12..16] (pa_w, pa_b, R6_d/h/w) are mathematically dead:
    //   pos_attn adds a per-row constant under softmax; R is orthogonal so q.k is invariant.
    const float* proj_w= (const float*)d_in[17];
    const float* proj_b= (const float*)d_in[18];
    float* out = (float*)d_out;

    prep_w27 <<<(27*96*96+255)/256, 256>>>(lp1_w);
    prep_pad <<<(int)(((size_t)BB*96*42*42*44 + 255)/256), 256>>>(pe);
    prep_fold<<<(96*96+255)/256,    256>>>(mod1_w, lp2_w, lp2_b, mod1_b);
    prep_trans<<<(96*288+255)/256,  256>>>(mod2_w, qkv_w, proj_w);

    // t1 = conv3(pos_emb) -> buf0
    conv3_kernel<<<dim3(20,40,BB), 96>>>(lp1_b);
    in_stats<0,1><<<BB*CC, 256>>>();
    // u = Wc @ gelu(IN(t1)) + bc -> buf1
    gemm_kernel<1,0,0,0,1,1,1><<<dim3(500,1,BB), 192>>>(96, nullptr, nullptr, nullptr);
    in_stats<1,2><<<BB*CC, 256>>>();
    // xm = x * sigmoid(mod2 @ gelu(IN(u)) + b) -> buf0 (t1 dead)
    gemm_kernel<1,1,1,1,0,2,0><<<dim3(500,1,BB), 192>>>(96, nullptr, mod2_b, x);
    // qkv = qkv_w @ xm + qkv_b
    gemm_kernel<0,0,2,0,2,0,0><<<dim3(500,3,BB), 192>>>(288, nullptr, qkv_b, nullptr);
    // axial attention, accumulate into buf1 (u dead)
    attn_kernel<0,false><<<dim3(1600,NHD,BB), 128>>>();
    attn_kernel<1,true ><<<dim3(1600,NHD,BB), 128>>>();
    attn_kernel<2,true ><<<dim3(1600,NHD,BB), 128>>>();
    // out = proj @ o + proj_b
    gemm_kernel<0,0,3,1,3,0,0><<<dim3(500,1,BB), 192>>>(96, out, proj_b, nullptr);
}

// round 9
// speedup vs baseline: 1.0078x; 1.0078x over previous
#include <cuda_runtime.h>
#include <math.h>

#define SVOL 64000
#define BB   2
#define CC   96
#define NHD  4
#define HD   24
#define LAX  40

typedef unsigned long long ull;

// ---- scratch: __device__ globals (no allocation anywhere) ----
__device__ float g_buf0[BB*CC*SVOL];   // conv out t1 -> x*mod
__device__ float g_buf1[BB*CC*SVOL];   // u -> attention accumulator
__device__ float g_qkv [BB*288*SVOL];
__device__ float g_pad [(size_t)BB*96*42*42*44];   // circularly padded pos_emb
__device__ float g_mu1[BB*CC], g_rs1[BB*CC], g_mu2[BB*CC], g_rs2[BB*CC];
__device__ float g_W27  [27*96*96];
__device__ float g_WcT  [96*96];
__device__ float g_bc   [96];
__device__ float g_mod2T[96*96];
__device__ float g_qkvT [96*288];
__device__ float g_projT[96*96];

__device__ __forceinline__ float gelu_f(float v){
    return 0.5f*v*(1.0f + erff(v*0.70710678118654752f));
}
__device__ __forceinline__ ull pack_dup(float x){
    ull r; asm("mov.b64 %0, {%1, %1};" : "=l"(r) : "f"(x)); return r;
}
__device__ __forceinline__ void fma2(ull& d, ull a, ull b){
    asm("fma.rn.f32x2 %0, %1, %2, %0;" : "+l"(d) : "l"(a), "l"(b));
}
__device__ __forceinline__ void unpack2(float& lo, float& hi, ull v){
    asm("mov.b64 {%0, %1}, %2;" : "=f"(lo), "=f"(hi) : "l"(v));
}

// ---- weight / input prep ----
__global__ void prep_w27(const float* __restrict__ lp1_w){
    int tid = blockIdx.x*blockDim.x + threadIdx.x;
    if (tid < 27*96*96){
        int t = tid/(96*96); int r = tid%(96*96); int ic = r/96; int oc = r%96;
        g_W27[tid] = lp1_w[(oc*96+ic)*27 + t];
    }
}
__global__ void prep_pad(const float* __restrict__ pe){
    size_t idx = (size_t)blockIdx.x*256 + threadIdx.x;
    if (idx >= (size_t)BB*96*42*42*44) return;
    int pw = (int)(idx % 44); size_t r = idx/44;
    int ph = (int)(r % 42); r /= 42;
    int pd = (int)(r % 42); r /= 42;
    int c  = (int)(r % 96); int b = (int)(r/96);
    int d = (pd+39)%40, h = (ph+39)%40, w = (pw+39)%40;
    g_pad[idx] = pe[(size_t)(b*96+c)*SVOL + d*1600 + h*40 + w];
}
__global__ void prep_fold(const float* __restrict__ mod1_w, const float* __restrict__ lp2_w,
                          const float* __restrict__ lp2_b, const float* __restrict__ mod1_b){
    int tid = blockIdx.x*blockDim.x + threadIdx.x;
    if (tid < 96*96){
        int k = tid/96, m = tid%96;
        float s = 0.f;
        for (int o = 0; o < 96; o++) s += mod1_w[m*96+o]*lp2_w[o*96+k];
        g_WcT[k*96+m] = s;
        if (k == 0){
            float b2 = 0.f;
            for (int o = 0; o < 96; o++) b2 += mod1_w[m*96+o]*lp2_b[o];
            g_bc[m] = b2 + mod1_b[m];
        }
    }
}
__global__ void prep_trans(const float* __restrict__ mod2_w, const float* __restrict__ qkv_w,
                           const float* __restrict__ proj_w){
    int tid = blockIdx.x*blockDim.x + threadIdx.x;
    if (tid < 96*96){
        int k = tid/96, m = tid%96;
        g_mod2T[k*96+m] = mod2_w[m*96+k];
        g_projT[k*96+m] = proj_w[m*96+k];
    }
    if (tid < 96*288){
        int k = tid/288, m = tid%288;
        g_qkvT[k*288+m] = qkv_w[m*96+k];
    }
}

// ---- conv3x3x3 circular, f32x2 packed over oc pairs, padded input ----
// smem: Xs[16 ic][4 rows][44] = 11.3KB, Ws3[3 dx][16 ic][96 oc] = 18.4KB
__global__ __launch_bounds__(96) void conv3_kernel(const float* __restrict__ lp1_b){
    __shared__ float Xs [16*4*44];
    __shared__ float Ws3[3*16*96];
    int b = blockIdx.z, d = blockIdx.y, h0 = blockIdx.x*2;
    int tid = threadIdx.x;
    int tm = tid/8, tn = tid%8;       // tm: oc-octet 0..11, tn: col group 0..7
    int cb = tn*10;
    int g  = cb/40;                   // output row within 2-row tile
    int wb = cb%40;

    ull acc2[4][10];
    #pragma unroll
    for (int i=0;i<4;i++)
        #pragma unroll
        for (int j=0;j<10;j++) acc2[i][j] = 0ULL;

    for (int dz=0; dz<3; dz++){
        int pd = d + dz;              // padded depth index
        for (int kc=0; kc<6; kc++){
            __syncthreads();
            // stage Xs: 64 rows (16 ic x 4 padded h-rows) x 11 float4, contiguous
            for (int idx=tid; idx<704; idx+=96){
                int row = idx/11, q = idx - row*11;
                int ic = row>>2, rr = row&3;
                size_t src = (((size_t)(b*96 + kc*16 + ic)*42 + pd)*42 + (h0+rr))*44 + q*4;
                *reinterpret_cast<float4*>(&Xs[(ic*4+rr)*44 + q*4]) =
                    *reinterpret_cast<const float4*>(&g_pad[src]);
            }
            for (int dy=0; dy<3; dy++){
                int t0 = (dz*3+dy)*3;
                __syncthreads();
                for (int idx=tid; idx<1152; idx+=96){
                    int dx = idx/384, rr = idx - dx*384;
                    *reinterpret_cast<float4*>(&Ws3[dx*1536 + rr*4]) =
                        *reinterpret_cast<const float4*>(&g_W27[(size_t)(t0+dx)*9216 + kc*16*96 + rr*4]);
                }
                __syncthreads();
                for (int k=0;k<16;k++){
                    ull xp[12];
                    #pragma unroll
                    for (int l=0;l<12;l++)
                        xp[l] = pack_dup(Xs[(k*4 + g + dy)*44 + wb + l]);
                    #pragma unroll
                    for (int dx=0;dx<3;dx++){
                        const ull* wp = reinterpret_cast<const ull*>(&Ws3[dx*1536 + k*96 + tm*8]);
                        ull w2[4];
                        #pragma unroll
                        for (int i=0;i<4;i++) w2[i] = wp[i];
                        #pragma unroll
                        for (int i=0;i<4;i++)
                            #pragma unroll
                            for (int j=0;j<10;j++)
                                fma2(acc2[i][j], w2[i], xp[j+dx]);
                    }
                }
            }
        }
    }
    size_t obase = (size_t)b*CC*SVOL + d*1600 + (h0+g)*40 + wb;
    #pragma unroll
    for (int i=0;i<4;i++){
        int oc0 = tm*8 + 2*i;
        float b0 = lp1_b[oc0], b1 = lp1_b[oc0+1];
        #pragma unroll
        for (int j=0;j<10;j++){
            float lo, hi; unpack2(lo, hi, acc2[i][j]);
            g_buf0[obase + (size_t)oc0*SVOL + j]     = lo + b0;
            g_buf0[obase + (size_t)(oc0+1)*SVOL + j] = hi + b1;
        }
    }
}

// ---- per-(b,c) instance-norm stats ----
template<int SRC, int SET>
__global__ __launch_bounds__(256) void in_stats(){
    const float* src = (SRC==0) ? g_buf0 : g_buf1;
    float* mu = (SET==1) ? g_mu1 : g_mu2;
    float* rs = (SET==1) ? g_rs1 : g_rs2;
    int bc = blockIdx.x;
    const float* p = src + (size_t)bc*SVOL;
    float s=0.f, s2=0.f;
    for (int i=threadIdx.x; i<SVOL/4; i+=256){
        float4 v = reinterpret_cast<const float4*>(p)[i];
        s += v.x+v.y+v.z+v.w;
        s2 = fmaf(v.x,v.x,s2); s2 = fmaf(v.y,v.y,s2);
        s2 = fmaf(v.z,v.z,s2); s2 = fmaf(v.w,v.w,s2);
    }
    __shared__ float r1[256], r2[256];
    r1[threadIdx.x]=s; r2[threadIdx.x]=s2;
    __syncthreads();
    for (int off=128; off>0; off>>=1){
        if (threadIdx.x<off){ r1[threadIdx.x]+=r1[threadIdx.x+off]; r2[threadIdx.x]+=r2[threadIdx.x+off]; }
        __syncthreads();
    }
    if (threadIdx.x==0){
        float m = r1[0]*(1.0f/SVOL);
        float var = r2[0]*(1.0f/SVOL) - m*m;
        mu[bc]=m; rs[bc]=rsqrtf(var + 1e-5f);
    }
}

// ---- fused 1x1-conv GEMM, f32x2 packed over m pairs ----
template<int PRO, int EPI, int AW, int SRC, int DST, int SET, int BIASG>
__global__ __launch_bounds__(192) void gemm_kernel(
    int Mtotal, float* __restrict__ extY,
    const float* __restrict__ bias_ext,
    const float* __restrict__ gate)
{
    __shared__ float As[48*96];
    __shared__ float Xs[48*128];
    const float* AT = (AW==0) ? g_WcT : (AW==1) ? g_mod2T : (AW==2) ? g_qkvT : g_projT;
    const float* X  = (SRC==0) ? g_buf0 : g_buf1;
    float* Y = (DST==0) ? g_buf0 : (DST==1) ? g_buf1 : (DST==2) ? g_qkv : extY;
    const float* bias = (BIASG==1) ? g_bc : bias_ext;
    const float* mu = (SET==1) ? g_mu1 : g_mu2;
    const float* rs = (SET==1) ? g_rs1 : g_rs2;

    int b = blockIdx.z, m0 = blockIdx.y*96, n0 = blockIdx.x*128;
    int tid = threadIdx.x, tm = tid/16, tn = tid%16;   // 12 x 16
    const float* xb = X + (size_t)b*96*SVOL + n0;

    ull acc2[4][8];
    #pragma unroll
    for (int i=0;i<4;i++)
        #pragma unroll
        for (int j=0;j<8;j++) acc2[i][j]=0ULL;

    for (int kc=0; kc<2; kc++){
        __syncthreads();
        for (int idx=tid; idx<1152; idx+=192){
            int k = idx/24, mq = idx%24;
            *reinterpret_cast<float4*>(&As[k*96 + mq*4]) =
                *reinterpret_cast<const float4*>(&AT[(kc*48+k)*Mtotal + m0 + mq*4]);
        }
        for (int idx=tid; idx<1536; idx+=192){
            int k = idx/32, cq = idx%32;
            int kg = kc*48 + k;
            float4 v = *reinterpret_cast<const float4*>(&xb[(size_t)kg*SVOL + cq*4]);
            if (PRO==1){
                float m = mu[b*96+kg], r = rs[b*96+kg];
                v.x = gelu_f((v.x-m)*r); v.y = gelu_f((v.y-m)*r);
                v.z = gelu_f((v.z-m)*r); v.w = gelu_f((v.w-m)*r);
            }
            *reinterpret_cast<float4*>(&Xs[k*128 + cq*4]) = v;
        }
        __syncthreads();
        for (int k=0;k<48;k++){
            const ull* wp = reinterpret_cast<const ull*>(&As[k*96 + tm*8]);
            ull w2[4];
            #pragma unroll
            for (int i=0;i<4;i++) w2[i] = wp[i];
            float4 x0 = *reinterpret_cast<const float4*>(&Xs[k*128 + tn*8]);
            float4 x1 = *reinterpret_cast<const float4*>(&Xs[k*128 + tn*8 + 4]);
            ull xp[8] = { pack_dup(x0.x), pack_dup(x0.y), pack_dup(x0.z), pack_dup(x0.w),
                          pack_dup(x1.x), pack_dup(x1.y), pack_dup(x1.z), pack_dup(x1.w) };
            #pragma unroll
            for (int i=0;i<4;i++)
                #pragma unroll
                for (int j=0;j<8;j++) fma2(acc2[i][j], w2[i], xp[j]);
        }
    }

    #pragma unroll
    for (int i=0;i<4;i++){
        int m = m0 + tm*8 + 2*i;
        float bi0 = bias[m], bi1 = bias[m+1];
        #pragma unroll
        for (int j=0;j<8;j++){
            int col = n0 + tn*8 + j;
            float lo, hi; unpack2(lo, hi, acc2[i][j]);
            float r0 = lo + bi0, r1 = hi + bi1;
            if (EPI==1){
                float g0 = gate[((size_t)b*96 + m  )*SVOL + col];
                float g1 = gate[((size_t)b*96 + m+1)*SVOL + col];
                r0 = g0 * (1.0f/(1.0f + __expf(-r0)));
                r1 = g1 * (1.0f/(1.0f + __expf(-r1)));
            }
            Y[((size_t)b*Mtotal + m  )*SVOL + col] = r0;
            Y[((size_t)b*Mtotal + m+1)*SVOL + col] = r1;
        }
    }
}

// ---- axial attention (rotation + pos_attn mathematically eliminated); out -> g_buf1 ----
template<int AXIS, bool ACCUM>
__global__ __launch_bounds__(128) void attn_kernel(){
    __shared__ float qs[HD][LAX];
    __shared__ float ks[HD][LAX];
    __shared__ float vs[LAX][HD];
    __shared__ float ps[LAX][LAX];
    int line = blockIdx.x, head = blockIdx.y, b = blockIdx.z;
    int tid = threadIdx.x;
    int s0 = 0, stride = 1;
    if (AXIS==0){ int d=line/40, h=line%40; s0 = d*1600 + h*40; stride = 1;    }
    if (AXIS==1){ int d=line/40, w=line%40; s0 = d*1600 + w;    stride = 40;   }
    if (AXIS==2){ int h=line/40, w=line%40; s0 = h*40 + w;      stride = 1600; }
    const float* base = g_qkv + (size_t)b*288*SVOL;

    for (int idx=tid; idx<2*HD*LAX; idx+=128){
        int t = idx/960, r = idx%960, hd = r/40, l = r%40;
        float v = base[(size_t)((t*NHD+head)*HD + hd)*SVOL + s0 + l*stride];
        if (t==0) qs[hd][l]=v; else ks[hd][l]=v;
    }
    for (int idx=tid; idx<HD*LAX; idx+=128){
        int hd = idx/40, l = idx%40;
        vs[l][hd] = base[(size_t)((2*NHD+head)*HD + hd)*SVOL + s0 + l*stride];
    }
    __syncthreads();

    const float scale = 0.2041241452319315f;  // 24^-0.5
    for (int idx=tid; idx<400; idx+=128){
        int i = idx/10, j0 = (idx%10)*4;
        float a0=0.f,a1=0.f,a2=0.f,a3=0.f;
        #pragma unroll
        for (int hd=0; hd<HD; hd++){
            float qv = qs[hd][i];
            float4 kv = *reinterpret_cast<const float4*>(&ks[hd][j0]);
            a0 = fmaf(qv,kv.x,a0); a1 = fmaf(qv,kv.y,a1);
            a2 = fmaf(qv,kv.z,a2); a3 = fmaf(qv,kv.w,a3);
        }
        ps[i][j0+0]=a0*scale; ps[i][j0+1]=a1*scale;
        ps[i][j0+2]=a2*scale; ps[i][j0+3]=a3*scale;
    }
    __syncthreads();
    if (tid < 40){
        float mx = -1e30f;
        for (int j=0;j<40;j++) mx = fmaxf(mx, ps[tid][j]);
        float sum = 0.f;
        for (int j=0;j<40;j++){ float e = __expf(ps[tid][j]-mx); ps[tid][j]=e; sum+=e; }
        float inv = 1.0f/sum;
        for (int j=0;j<40;j++) ps[tid][j]*=inv;
    }
    __syncthreads();
    for (int idx=tid; idx<240; idx+=128){
        int i = idx/6, hd0 = (idx%6)*4;
        float a0=0.f,a1=0.f,a2=0.f,a3=0.f;
        #pragma unroll
        for (int j=0;j<40;j++){
            float pv = ps[i][j];
            float4 vv = *reinterpret_cast<const float4*>(&vs[j][hd0]);
            a0 = fmaf(pv,vv.x,a0); a1 = fmaf(pv,vv.y,a1);
            a2 = fmaf(pv,vv.z,a2); a3 = fmaf(pv,vv.w,a3);
        }
        float r[4] = {a0,a1,a2,a3};
        #pragma unroll
        for (int q=0;q<4;q++){
            size_t oi = ((size_t)b*CC + head*HD + hd0 + q)*SVOL + s0 + i*stride;
            if (ACCUM) g_buf1[oi] += r[q]; else g_buf1[oi] = r[q];
        }
    }
}

extern "C" void kernel_launch(void* const* d_in, const int* in_sizes, int n_in,
                              void* d_out, int out_size){
    const float* x     = (const float*)d_in[0];
    const float* pe    = (const float*)d_in[1];
    const float* qkv_w = (const float*)d_in[2];
    const float* qkv_b = (const float*)d_in[3];
    const float* lp1_w = (const float*)d_in[4];
    const float* lp1_b = (const float*)d_in[5];
    const float* lp2_w = (const float*)d_in[6];
    const float* lp2_b = (const float*)d_in[7];
    const float* mod1_w= (const float*)d_in[8];
    const float* mod1_b= (const float*)d_in[9];
    const float* mod2_w= (const float*)d_in[10];
    const float* mod2_b= (const float*)d_in[11];
    // d_in[12..16] (pa_w, pa_b, R6_d/h/w) are mathematically dead:
    //   pos_attn adds a per-row constant under softmax; R is orthogonal so q.k is invariant.
    const float* proj_w= (const float*)d_in[17];
    const float* proj_b= (const float*)d_in[18];
    float* out = (float*)d_out;

    prep_w27 <<<(27*96*96+255)/256, 256>>>(lp1_w);
    prep_pad <<<(int)(((size_t)BB*96*42*42*44 + 255)/256), 256>>>(pe);
    prep_fold<<<(96*96+255)/256,    256>>>(mod1_w, lp2_w, lp2_b, mod1_b);
    prep_trans<<<(96*288+255)/256,  256>>>(mod2_w, qkv_w, proj_w);

    // t1 = conv3(pos_emb) -> buf0
    conv3_kernel<<<dim3(20,40,BB), 96>>>(lp1_b);
    in_stats<0,1><<<BB*CC, 256>>>();
    // u = Wc @ gelu(IN(t1)) + bc -> buf1
    gemm_kernel<1,0,0,0,1,1,1><<<dim3(500,1,BB), 192>>>(96, nullptr, nullptr, nullptr);
    in_stats<1,2><<<BB*CC, 256>>>();
    // xm = x * sigmoid(mod2 @ gelu(IN(u)) + b) -> buf0 (t1 dead)
    gemm_kernel<1,1,1,1,0,2,0><<<dim3(500,1,BB), 192>>>(96, nullptr, mod2_b, x);
    // qkv = qkv_w @ xm + qkv_b
    gemm_kernel<0,0,2,0,2,0,0><<<dim3(500,3,BB), 192>>>(288, nullptr, qkv_b, nullptr);
    // axial attention, accumulate into buf1 (u dead)
    attn_kernel<0,false><<<dim3(1600,NHD,BB), 128>>>();
    attn_kernel<1,true ><<<dim3(1600,NHD,BB), 128>>>();
    attn_kernel<2,true ><<<dim3(1600,NHD,BB), 128>>>();
    // out = proj @ o + proj_b
    gemm_kernel<0,0,3,1,3,0,0><<<dim3(500,1,BB), 192>>>(96, out, proj_b, nullptr);
}

// round 10
// speedup vs baseline: 1.0145x; 1.0067x over previous
#include <cuda_runtime.h>
#include <math.h>

#define SVOL 64000
#define BB   2
#define CC   96
#define NHD  4
#define HD   24
#define LAX  40

typedef unsigned long long ull;

// ---- scratch: __device__ globals (no allocation anywhere) ----
__device__ float g_buf0[BB*CC*SVOL];   // conv out t1 -> x*mod
__device__ float g_buf1[BB*CC*SVOL];   // u -> attention accumulator
__device__ float g_qkv [BB*288*SVOL];
__device__ float g_pad [(size_t)BB*96*42*42*44];   // circularly padded pos_emb
__device__ float g_mu1[BB*CC], g_rs1[BB*CC], g_mu2[BB*CC], g_rs2[BB*CC];
__device__ float g_W27  [27*96*96];
__device__ float g_WcT  [96*96];
__device__ float g_bc   [96];
__device__ float g_mod2T[96*96];
__device__ float g_qkvT [96*288];
__device__ float g_projT[96*96];

__device__ __forceinline__ float gelu_f(float v){
    return 0.5f*v*(1.0f + erff(v*0.70710678118654752f));
}
__device__ __forceinline__ ull pack_dup(float x){
    ull r; asm("mov.b64 %0, {%1, %1};" : "=l"(r) : "f"(x)); return r;
}
__device__ __forceinline__ void fma2(ull& d, ull a, ull b){
    asm("fma.rn.f32x2 %0, %1, %2, %0;" : "+l"(d) : "l"(a), "l"(b));
}
__device__ __forceinline__ void unpack2(float& lo, float& hi, ull v){
    asm("mov.b64 {%0, %1}, %2;" : "=f"(lo), "=f"(hi) : "l"(v));
}

// ---- weight / input prep ----
__global__ void prep_w27(const float* __restrict__ lp1_w){
    int tid = blockIdx.x*blockDim.x + threadIdx.x;
    if (tid < 27*96*96){
        int t = tid/(96*96); int r = tid%(96*96); int ic = r/96; int oc = r%96;
        g_W27[tid] = lp1_w[(oc*96+ic)*27 + t];
    }
}
__global__ void prep_pad(const float* __restrict__ pe){
    size_t idx = (size_t)blockIdx.x*256 + threadIdx.x;
    if (idx >= (size_t)BB*96*42*42*44) return;
    int pw = (int)(idx % 44); size_t r = idx/44;
    int ph = (int)(r % 42); r /= 42;
    int pd = (int)(r % 42); r /= 42;
    int c  = (int)(r % 96); int b = (int)(r/96);
    int d = (pd+39)%40, h = (ph+39)%40, w = (pw+39)%40;
    g_pad[idx] = pe[(size_t)(b*96+c)*SVOL + d*1600 + h*40 + w];
}
__global__ void prep_fold(const float* __restrict__ mod1_w, const float* __restrict__ lp2_w,
                          const float* __restrict__ lp2_b, const float* __restrict__ mod1_b){
    int tid = blockIdx.x*blockDim.x + threadIdx.x;
    if (tid < 96*96){
        int k = tid/96, m = tid%96;
        float s = 0.f;
        for (int o = 0; o < 96; o++) s += mod1_w[m*96+o]*lp2_w[o*96+k];
        g_WcT[k*96+m] = s;
        if (k == 0){
            float b2 = 0.f;
            for (int o = 0; o < 96; o++) b2 += mod1_w[m*96+o]*lp2_b[o];
            g_bc[m] = b2 + mod1_b[m];
        }
    }
}
__global__ void prep_trans(const float* __restrict__ mod2_w, const float* __restrict__ qkv_w,
                           const float* __restrict__ proj_w){
    int tid = blockIdx.x*blockDim.x + threadIdx.x;
    if (tid < 96*96){
        int k = tid/96, m = tid%96;
        g_mod2T[k*96+m] = mod2_w[m*96+k];
        g_projT[k*96+m] = proj_w[m*96+k];
    }
    if (tid < 96*288){
        int k = tid/288, m = tid%288;
        g_qkvT[k*288+m] = qkv_w[m*96+k];
    }
}

// ---- conv3x3x3 circular, f32x2 packed over oc pairs, padded input ----
// smem: Xs[16 ic][4 rows][44] = 11.3KB, Ws3[3 dx][16 ic][96 oc] = 18.4KB
__global__ __launch_bounds__(96) void conv3_kernel(const float* __restrict__ lp1_b){
    __shared__ float Xs [16*4*44];
    __shared__ float Ws3[3*16*96];
    int b = blockIdx.z, d = blockIdx.y, h0 = blockIdx.x*2;
    int tid = threadIdx.x;
    int tm = tid/8, tn = tid%8;       // tm: oc-octet 0..11, tn: col group 0..7
    int cb = tn*10;
    int g  = cb/40;                   // output row within 2-row tile
    int wb = cb%40;

    ull acc2[4][10];
    #pragma unroll
    for (int i=0;i<4;i++)
        #pragma unroll
        for (int j=0;j<10;j++) acc2[i][j] = 0ULL;

    for (int dz=0; dz<3; dz++){
        int pd = d + dz;              // padded depth index
        for (int kc=0; kc<6; kc++){
            __syncthreads();
            // stage Xs: 64 rows (16 ic x 4 padded h-rows) x 11 float4, contiguous
            for (int idx=tid; idx<704; idx+=96){
                int row = idx/11, q = idx - row*11;
                int ic = row>>2, rr = row&3;
                size_t src = (((size_t)(b*96 + kc*16 + ic)*42 + pd)*42 + (h0+rr))*44 + q*4;
                *reinterpret_cast<float4*>(&Xs[(ic*4+rr)*44 + q*4]) =
                    *reinterpret_cast<const float4*>(&g_pad[src]);
            }
            for (int dy=0; dy<3; dy++){
                int t0 = (dz*3+dy)*3;
                __syncthreads();
                for (int idx=tid; idx<1152; idx+=96){
                    int dx = idx/384, rr = idx - dx*384;
                    *reinterpret_cast<float4*>(&Ws3[dx*1536 + rr*4]) =
                        *reinterpret_cast<const float4*>(&g_W27[(size_t)(t0+dx)*9216 + kc*16*96 + rr*4]);
                }
                __syncthreads();
                for (int k=0;k<16;k++){
                    ull xp[12];
                    #pragma unroll
                    for (int l=0;l<12;l++)
                        xp[l] = pack_dup(Xs[(k*4 + g + dy)*44 + wb + l]);
                    #pragma unroll
                    for (int dx=0;dx<3;dx++){
                        const ull* wp = reinterpret_cast<const ull*>(&Ws3[dx*1536 + k*96 + tm*8]);
                        ull w2[4];
                        #pragma unroll
                        for (int i=0;i<4;i++) w2[i] = wp[i];
                        #pragma unroll
                        for (int i=0;i<4;i++)
                            #pragma unroll
                            for (int j=0;j<10;j++)
                                fma2(acc2[i][j], w2[i], xp[j+dx]);
                    }
                }
            }
        }
    }
    size_t obase = (size_t)b*CC*SVOL + d*1600 + (h0+g)*40 + wb;
    #pragma unroll
    for (int i=0;i<4;i++){
        int oc0 = tm*8 + 2*i;
        float b0 = lp1_b[oc0], b1 = lp1_b[oc0+1];
        #pragma unroll
        for (int j=0;j<10;j++){
            float lo, hi; unpack2(lo, hi, acc2[i][j]);
            g_buf0[obase + (size_t)oc0*SVOL + j]     = lo + b0;
            g_buf0[obase + (size_t)(oc0+1)*SVOL + j] = hi + b1;
        }
    }
}

// ---- per-(b,c) instance-norm stats ----
template<int SRC, int SET>
__global__ __launch_bounds__(256) void in_stats(){
    const float* src = (SRC==0) ? g_buf0 : g_buf1;
    float* mu = (SET==1) ? g_mu1 : g_mu2;
    float* rs = (SET==1) ? g_rs1 : g_rs2;
    int bc = blockIdx.x;
    const float* p = src + (size_t)bc*SVOL;
    float s=0.f, s2=0.f;
    for (int i=threadIdx.x; i<SVOL/4; i+=256){
        float4 v = reinterpret_cast<const float4*>(p)[i];
        s += v.x+v.y+v.z+v.w;
        s2 = fmaf(v.x,v.x,s2); s2 = fmaf(v.y,v.y,s2);
        s2 = fmaf(v.z,v.z,s2); s2 = fmaf(v.w,v.w,s2);
    }
    __shared__ float r1[256], r2[256];
    r1[threadIdx.x]=s; r2[threadIdx.x]=s2;
    __syncthreads();
    for (int off=128; off>0; off>>=1){
        if (threadIdx.x<off){ r1[threadIdx.x]+=r1[threadIdx.x+off]; r2[threadIdx.x]+=r2[threadIdx.x+off]; }
        __syncthreads();
    }
    if (threadIdx.x==0){
        float m = r1[0]*(1.0f/SVOL);
        float var = r2[0]*(1.0f/SVOL) - m*m;
        mu[bc]=m; rs[bc]=rsqrtf(var + 1e-5f);
    }
}

// ---- fused 1x1-conv GEMM, f32x2 packed over m pairs ----
template<int PRO, int EPI, int AW, int SRC, int DST, int SET, int BIASG>
__global__ __launch_bounds__(192) void gemm_kernel(
    int Mtotal, float* __restrict__ extY,
    const float* __restrict__ bias_ext,
    const float* __restrict__ gate)
{
    __shared__ float As[48*96];
    __shared__ float Xs[48*128];
    const float* AT = (AW==0) ? g_WcT : (AW==1) ? g_mod2T : (AW==2) ? g_qkvT : g_projT;
    const float* X  = (SRC==0) ? g_buf0 : g_buf1;
    float* Y = (DST==0) ? g_buf0 : (DST==1) ? g_buf1 : (DST==2) ? g_qkv : extY;
    const float* bias = (BIASG==1) ? g_bc : bias_ext;
    const float* mu = (SET==1) ? g_mu1 : g_mu2;
    const float* rs = (SET==1) ? g_rs1 : g_rs2;

    int b = blockIdx.z, m0 = blockIdx.y*96, n0 = blockIdx.x*128;
    int tid = threadIdx.x, tm = tid/16, tn = tid%16;   // 12 x 16
    const float* xb = X + (size_t)b*96*SVOL + n0;

    ull acc2[4][8];
    #pragma unroll
    for (int i=0;i<4;i++)
        #pragma unroll
        for (int j=0;j<8;j++) acc2[i][j]=0ULL;

    for (int kc=0; kc<2; kc++){
        __syncthreads();
        for (int idx=tid; idx<1152; idx+=192){
            int k = idx/24, mq = idx%24;
            *reinterpret_cast<float4*>(&As[k*96 + mq*4]) =
                *reinterpret_cast<const float4*>(&AT[(kc*48+k)*Mtotal + m0 + mq*4]);
        }
        for (int idx=tid; idx<1536; idx+=192){
            int k = idx/32, cq = idx%32;
            int kg = kc*48 + k;
            float4 v = *reinterpret_cast<const float4*>(&xb[(size_t)kg*SVOL + cq*4]);
            if (PRO==1){
                float m = mu[b*96+kg], r = rs[b*96+kg];
                v.x = gelu_f((v.x-m)*r); v.y = gelu_f((v.y-m)*r);
                v.z = gelu_f((v.z-m)*r); v.w = gelu_f((v.w-m)*r);
            }
            *reinterpret_cast<float4*>(&Xs[k*128 + cq*4]) = v;
        }
        __syncthreads();
        for (int k=0;k<48;k++){
            const ull* wp = reinterpret_cast<const ull*>(&As[k*96 + tm*8]);
            ull w2[4];
            #pragma unroll
            for (int i=0;i<4;i++) w2[i] = wp[i];
            float4 x0 = *reinterpret_cast<const float4*>(&Xs[k*128 + tn*8]);
            float4 x1 = *reinterpret_cast<const float4*>(&Xs[k*128 + tn*8 + 4]);
            ull xp[8] = { pack_dup(x0.x), pack_dup(x0.y), pack_dup(x0.z), pack_dup(x0.w),
                          pack_dup(x1.x), pack_dup(x1.y), pack_dup(x1.z), pack_dup(x1.w) };
            #pragma unroll
            for (int i=0;i<4;i++)
                #pragma unroll
                for (int j=0;j<8;j++) fma2(acc2[i][j], w2[i], xp[j]);
        }
    }

    #pragma unroll
    for (int i=0;i<4;i++){
        int m = m0 + tm*8 + 2*i;
        float bi0 = bias[m], bi1 = bias[m+1];
        #pragma unroll
        for (int j=0;j<8;j++){
            int col = n0 + tn*8 + j;
            float lo, hi; unpack2(lo, hi, acc2[i][j]);
            float r0 = lo + bi0, r1 = hi + bi1;
            if (EPI==1){
                float g0 = gate[((size_t)b*96 + m  )*SVOL + col];
                float g1 = gate[((size_t)b*96 + m+1)*SVOL + col];
                r0 = g0 * (1.0f/(1.0f + __expf(-r0)));
                r1 = g1 * (1.0f/(1.0f + __expf(-r1)));
            }
            Y[((size_t)b*Mtotal + m  )*SVOL + col] = r0;
            Y[((size_t)b*Mtotal + m+1)*SVOL + col] = r1;
        }
    }
}

// ---- axial attention (rotation + pos_attn mathematically eliminated); out -> g_buf1 ----
template<int AXIS, bool ACCUM>
__global__ __launch_bounds__(128) void attn_kernel(){
    __shared__ float qs[HD][LAX];
    __shared__ float ks[HD][LAX];
    __shared__ float vs[LAX][HD];
    __shared__ float ps[LAX][LAX];
    int line = blockIdx.x, head = blockIdx.y, b = blockIdx.z;
    int tid = threadIdx.x;
    int s0 = 0, stride = 1;
    if (AXIS==0){ int d=line/40, h=line%40; s0 = d*1600 + h*40; stride = 1;    }
    if (AXIS==1){ int d=line/40, w=line%40; s0 = d*1600 + w;    stride = 40;   }
    if (AXIS==2){ int h=line/40, w=line%40; s0 = h*40 + w;      stride = 1600; }
    const float* base = g_qkv + (size_t)b*288*SVOL;

    for (int idx=tid; idx<2*HD*LAX; idx+=128){
        int t = idx/960, r = idx%960, hd = r/40, l = r%40;
        float v = base[(size_t)((t*NHD+head)*HD + hd)*SVOL + s0 + l*stride];
        if (t==0) qs[hd][l]=v; else ks[hd][l]=v;
    }
    for (int idx=tid; idx<HD*LAX; idx+=128){
        int hd = idx/40, l = idx%40;
        vs[l][hd] = base[(size_t)((2*NHD+head)*HD + hd)*SVOL + s0 + l*stride];
    }
    __syncthreads();

    const float scale = 0.2041241452319315f;  // 24^-0.5
    for (int idx=tid; idx<400; idx+=128){
        int i = idx/10, j0 = (idx%10)*4;
        float a0=0.f,a1=0.f,a2=0.f,a3=0.f;
        #pragma unroll
        for (int hd=0; hd<HD; hd++){
            float qv = qs[hd][i];
            float4 kv = *reinterpret_cast<const float4*>(&ks[hd][j0]);
            a0 = fmaf(qv,kv.x,a0); a1 = fmaf(qv,kv.y,a1);
            a2 = fmaf(qv,kv.z,a2); a3 = fmaf(qv,kv.w,a3);
        }
        ps[i][j0+0]=a0*scale; ps[i][j0+1]=a1*scale;
        ps[i][j0+2]=a2*scale; ps[i][j0+3]=a3*scale;
    }
    __syncthreads();
    if (tid < 40){
        float mx = -1e30f;
        for (int j=0;j<40;j++) mx = fmaxf(mx, ps[tid][j]);
        float sum = 0.f;
        for (int j=0;j<40;j++){ float e = __expf(ps[tid][j]-mx); ps[tid][j]=e; sum+=e; }
        float inv = 1.0f/sum;
        for (int j=0;j<40;j++) ps[tid][j]*=inv;
    }
    __syncthreads();
    for (int idx=tid; idx<240; idx+=128){
        int i = idx/6, hd0 = (idx%6)*4;
        float a0=0.f,a1=0.f,a2=0.f,a3=0.f;
        #pragma unroll
        for (int j=0;j<40;j++){
            float pv = ps[i][j];
            float4 vv = *reinterpret_cast<const float4*>(&vs[j][hd0]);
            a0 = fmaf(pv,vv.x,a0); a1 = fmaf(pv,vv.y,a1);
            a2 = fmaf(pv,vv.z,a2); a3 = fmaf(pv,vv.w,a3);
        }
        float r[4] = {a0,a1,a2,a3};
        #pragma unroll
        for (int q=0;q<4;q++){
            size_t oi = ((size_t)b*CC + head*HD + hd0 + q)*SVOL + s0 + i*stride;
            if (ACCUM) g_buf1[oi] += r[q]; else g_buf1[oi] = r[q];
        }
    }
}

extern "C" void kernel_launch(void* const* d_in, const int* in_sizes, int n_in,
                              void* d_out, int out_size){
    const float* x     = (const float*)d_in[0];
    const float* pe    = (const float*)d_in[1];
    const float* qkv_w = (const float*)d_in[2];
    const float* qkv_b = (const float*)d_in[3];
    const float* lp1_w = (const float*)d_in[4];
    const float* lp1_b = (const float*)d_in[5];
    const float* lp2_w = (const float*)d_in[6];
    const float* lp2_b = (const float*)d_in[7];
    const float* mod1_w= (const float*)d_in[8];
    const float* mod1_b= (const float*)d_in[9];
    const float* mod2_w= (const float*)d_in[10];
    const float* mod2_b= (const float*)d_in[11];
    // d_in[12..16] (pa_w, pa_b, R6_d/h/w) are mathematically dead:
    //   pos_attn adds a per-row constant under softmax; R is orthogonal so q.k is invariant.
    const float* proj_w= (const float*)d_in[17];
    const float* proj_b= (const float*)d_in[18];
    float* out = (float*)d_out;

    prep_w27 <<<(27*96*96+255)/256, 256>>>(lp1_w);
    prep_pad <<<(int)(((size_t)BB*96*42*42*44 + 255)/256), 256>>>(pe);
    prep_fold<<<(96*96+255)/256,    256>>>(mod1_w, lp2_w, lp2_b, mod1_b);
    prep_trans<<<(96*288+255)/256,  256>>>(mod2_w, qkv_w, proj_w);

    // t1 = conv3(pos_emb) -> buf0
    conv3_kernel<<<dim3(20,40,BB), 96>>>(lp1_b);
    in_stats<0,1><<<BB*CC, 256>>>();
    // u = Wc @ gelu(IN(t1)) + bc -> buf1
    gemm_kernel<1,0,0,0,1,1,1><<<dim3(500,1,BB), 192>>>(96, nullptr, nullptr, nullptr);
    in_stats<1,2><<<BB*CC, 256>>>();
    // xm = x * sigmoid(mod2 @ gelu(IN(u)) + b) -> buf0 (t1 dead)
    gemm_kernel<1,1,1,1,0,2,0><<<dim3(500,1,BB), 192>>>(96, nullptr, mod2_b, x);
    // qkv = qkv_w @ xm + qkv_b
    gemm_kernel<0,0,2,0,2,0,0><<<dim3(500,3,BB), 192>>>(288, nullptr, qkv_b, nullptr);
    // axial attention, accumulate into buf1 (u dead)
    attn_kernel<0,false><<<dim3(1600,NHD,BB), 128>>>();
    attn_kernel<1,true ><<<dim3(1600,NHD,BB), 128>>>();
    attn_kernel<2,true ><<<dim3(1600,NHD,BB), 128>>>();
    // out = proj @ o + proj_b
    gemm_kernel<0,0,3,1,3,0,0><<<dim3(500,1,BB), 192>>>(96, out, proj_b, nullptr);
}

// round 13
// speedup vs baseline: 1.4227x; 1.4024x over previous
#include <cuda_runtime.h>
#include <math.h>

#define SVOL 64000
#define BB   2
#define CC   96
#define NHD  4
#define HD   24
#define LAX  40

typedef unsigned long long ull;

// ---- scratch: __device__ globals (no allocation anywhere) ----
__device__ float g_buf0[BB*CC*SVOL];   // conv out t1 -> x*mod
__device__ float g_buf1[BB*CC*SVOL];   // u -> attention accumulator
__device__ float g_qkv [BB*288*SVOL];  // std layout: d*1600 + h*40 + w
__device__ float g_qkvA[BB*288*SVOL];  // h-fastest:  d*1600 + w*40 + h
__device__ float g_qkvB[BB*288*SVOL];  // d-fastest:  h*1600 + w*40 + d
__device__ float g_oA  [BB*CC*SVOL];   // axis1 out (A layout)
__device__ float g_oB  [BB*CC*SVOL];   // axis2 out (B layout)
__device__ float g_pad [(size_t)BB*96*42*42*44];   // circularly padded pos_emb
__device__ float g_mu1[BB*CC], g_rs1[BB*CC], g_mu2[BB*CC], g_rs2[BB*CC];
__device__ float g_W27  [27*96*96];
__device__ float g_WcT  [96*96];
__device__ float g_bc   [96];
__device__ float g_mod2T[96*96];
__device__ float g_qkvT [96*288];
__device__ float g_projT[96*96];

__device__ __forceinline__ float gelu_f(float v){
    return 0.5f*v*(1.0f + erff(v*0.70710678118654752f));
}
__device__ __forceinline__ ull pack_dup(float x){
    ull r; asm("mov.b64 %0, {%1, %1};" : "=l"(r) : "f"(x)); return r;
}
__device__ __forceinline__ void fma2(ull& d, ull a, ull b){
    asm("fma.rn.f32x2 %0, %1, %2, %0;" : "+l"(d) : "l"(a), "l"(b));
}
__device__ __forceinline__ void unpack2(float& lo, float& hi, ull v){
    asm("mov.b64 {%0, %1}, %2;" : "=f"(lo), "=f"(hi) : "l"(v));
}

// ---- weight / input prep ----
__global__ void prep_w27(const float* __restrict__ lp1_w){
    int tid = blockIdx.x*blockDim.x + threadIdx.x;
    if (tid < 27*96*96){
        int t = tid/(96*96); int r = tid%(96*96); int ic = r/96; int oc = r%96;
        g_W27[tid] = lp1_w[(oc*96+ic)*27 + t];
    }
}
__global__ void prep_pad(const float* __restrict__ pe){
    size_t idx = (size_t)blockIdx.x*256 + threadIdx.x;
    if (idx >= (size_t)BB*96*42*42*44) return;
    int pw = (int)(idx % 44); size_t r = idx/44;
    int ph = (int)(r % 42); r /= 42;
    int pd = (int)(r % 42); r /= 42;
    int c  = (int)(r % 96); int b = (int)(r/96);
    int d = (pd+39)%40, h = (ph+39)%40, w = (pw+39)%40;
    g_pad[idx] = pe[(size_t)(b*96+c)*SVOL + d*1600 + h*40 + w];
}
__global__ void prep_fold(const float* __restrict__ mod1_w, const float* __restrict__ lp2_w,
                          const float* __restrict__ lp2_b, const float* __restrict__ mod1_b){
    int tid = blockIdx.x*blockDim.x + threadIdx.x;
    if (tid < 96*96){
        int k = tid/96, m = tid%96;
        float s = 0.f;
        for (int o = 0; o < 96; o++) s += mod1_w[m*96+o]*lp2_w[o*96+k];
        g_WcT[k*96+m] = s;
        if (k == 0){
            float b2 = 0.f;
            for (int o = 0; o < 96; o++) b2 += mod1_w[m*96+o]*lp2_b[o];
            g_bc[m] = b2 + mod1_b[m];
        }
    }
}
__global__ void prep_trans(const float* __restrict__ mod2_w, const float* __restrict__ qkv_w,
                           const float* __restrict__ proj_w){
    int tid = blockIdx.x*blockDim.x + threadIdx.x;
    if (tid < 96*96){
        int k = tid/96, m = tid%96;
        g_mod2T[k*96+m] = mod2_w[m*96+k];
        g_projT[k*96+m] = proj_w[m*96+k];
    }
    if (tid < 96*288){
        int k = tid/288, m = tid%288;
        g_qkvT[k*288+m] = qkv_w[m*96+k];
    }
}

// ---- conv3x3x3 circular, f32x2 packed over oc pairs, padded input ----
__global__ __launch_bounds__(96) void conv3_kernel(const float* __restrict__ lp1_b){
    __shared__ float Xs [16*4*44];
    __shared__ float Ws3[3*16*96];
    int b = blockIdx.z, d = blockIdx.y, h0 = blockIdx.x*2;
    int tid = threadIdx.x;
    int tm = tid/8, tn = tid%8;
    int cb = tn*10;
    int g  = cb/40;
    int wb = cb%40;

    ull acc2[4][10];
    #pragma unroll
    for (int i=0;i<4;i++)
        #pragma unroll
        for (int j=0;j<10;j++) acc2[i][j] = 0ULL;

    for (int dz=0; dz<3; dz++){
        int pd = d + dz;
        for (int kc=0; kc<6; kc++){
            __syncthreads();
            for (int idx=tid; idx<704; idx+=96){
                int row = idx/11, q = idx - row*11;
                int ic = row>>2, rr = row&3;
                size_t src = (((size_t)(b*96 + kc*16 + ic)*42 + pd)*42 + (h0+rr))*44 + q*4;
                *reinterpret_cast<float4*>(&Xs[(ic*4+rr)*44 + q*4]) =
                    *reinterpret_cast<const float4*>(&g_pad[src]);
            }
            for (int dy=0; dy<3; dy++){
                int t0 = (dz*3+dy)*3;
                __syncthreads();
                for (int idx=tid; idx<1152; idx+=96){
                    int dx = idx/384, rr = idx - dx*384;
                    *reinterpret_cast<float4*>(&Ws3[dx*1536 + rr*4]) =
                        *reinterpret_cast<const float4*>(&g_W27[(size_t)(t0+dx)*9216 + kc*16*96 + rr*4]);
                }
                __syncthreads();
                for (int k=0;k<16;k++){
                    ull xp[12];
                    #pragma unroll
                    for (int l=0;l<12;l++)
                        xp[l] = pack_dup(Xs[(k*4 + g + dy)*44 + wb + l]);
                    #pragma unroll
                    for (int dx=0;dx<3;dx++){
                        const ull* wp = reinterpret_cast<const ull*>(&Ws3[dx*1536 + k*96 + tm*8]);
                        ull w2[4];
                        #pragma unroll
                        for (int i=0;i<4;i++) w2[i] = wp[i];
                        #pragma unroll
                        for (int i=0;i<4;i++)
                            #pragma unroll
                            for (int j=0;j<10;j++)
                                fma2(acc2[i][j], w2[i], xp[j+dx]);
                    }
                }
            }
        }
    }
    size_t obase = (size_t)b*CC*SVOL + d*1600 + (h0+g)*40 + wb;
    #pragma unroll
    for (int i=0;i<4;i++){
        int oc0 = tm*8 + 2*i;
        float b0 = lp1_b[oc0], b1 = lp1_b[oc0+1];
        #pragma unroll
        for (int j=0;j<10;j++){
            float lo, hi; unpack2(lo, hi, acc2[i][j]);
            g_buf0[obase + (size_t)oc0*SVOL + j]     = lo + b0;
            g_buf0[obase + (size_t)(oc0+1)*SVOL + j] = hi + b1;
        }
    }
}

// ---- per-(b,c) instance-norm stats ----
template<int SRC, int SET>
__global__ __launch_bounds__(256) void in_stats(){
    const float* src = (SRC==0) ? g_buf0 : g_buf1;
    float* mu = (SET==1) ? g_mu1 : g_mu2;
    float* rs = (SET==1) ? g_rs1 : g_rs2;
    int bc = blockIdx.x;
    const float* p = src + (size_t)bc*SVOL;
    float s=0.f, s2=0.f;
    for (int i=threadIdx.x; i<SVOL/4; i+=256){
        float4 v = reinterpret_cast<const float4*>(p)[i];
        s += v.x+v.y+v.z+v.w;
        s2 = fmaf(v.x,v.x,s2); s2 = fmaf(v.y,v.y,s2);
        s2 = fmaf(v.z,v.z,s2); s2 = fmaf(v.w,v.w,s2);
    }
    __shared__ float r1[256], r2[256];
    r1[threadIdx.x]=s; r2[threadIdx.x]=s2;
    __syncthreads();
    for (int off=128; off>0; off>>=1){
        if (threadIdx.x<off){ r1[threadIdx.x]+=r1[threadIdx.x+off]; r2[threadIdx.x]+=r2[threadIdx.x+off]; }
        __syncthreads();
    }
    if (threadIdx.x==0){
        float m = r1[0]*(1.0f/SVOL);
        float var = r2[0]*(1.0f/SVOL) - m*m;
        mu[bc]=m; rs[bc]=rsqrtf(var + 1e-5f);
    }
}

// ---- fused 1x1-conv GEMM, f32x2 packed over m pairs ----
template<int PRO, int EPI, int AW, int SRC, int DST, int SET, int BIASG>
__global__ __launch_bounds__(192) void gemm_kernel(
    int Mtotal, float* __restrict__ extY,
    const float* __restrict__ bias_ext,
    const float* __restrict__ gate)
{
    __shared__ float As[48*96];
    __shared__ float Xs[48*128];
    const float* AT = (AW==0) ? g_WcT : (AW==1) ? g_mod2T : (AW==2) ? g_qkvT : g_projT;
    const float* X  = (SRC==0) ? g_buf0 : g_buf1;
    float* Y = (DST==0) ? g_buf0 : (DST==1) ? g_buf1 : (DST==2) ? g_qkv : extY;
    const float* bias = (BIASG==1) ? g_bc : bias_ext;
    const float* mu = (SET==1) ? g_mu1 : g_mu2;
    const float* rs = (SET==1) ? g_rs1 : g_rs2;

    int b = blockIdx.z, m0 = blockIdx.y*96, n0 = blockIdx.x*128;
    int tid = threadIdx.x, tm = tid/16, tn = tid%16;
    const float* xb = X + (size_t)b*96*SVOL + n0;

    ull acc2[4][8];
    #pragma unroll
    for (int i=0;i<4;i++)
        #pragma unroll
        for (int j=0;j<8;j++) acc2[i][j]=0ULL;

    for (int kc=0; kc<2; kc++){
        __syncthreads();
        for (int idx=tid; idx<1152; idx+=192){
            int k = idx/24, mq = idx%24;
            *reinterpret_cast<float4*>(&As[k*96 + mq*4]) =
                *reinterpret_cast<const float4*>(&AT[(kc*48+k)*Mtotal + m0 + mq*4]);
        }
        for (int idx=tid; idx<1536; idx+=192){
            int k = idx/32, cq = idx%32;
            int kg = kc*48 + k;
            float4 v = *reinterpret_cast<const float4*>(&xb[(size_t)kg*SVOL + cq*4]);
            if (PRO==1){
                float m = mu[b*96+kg], r = rs[b*96+kg];
                v.x = gelu_f((v.x-m)*r); v.y = gelu_f((v.y-m)*r);
                v.z = gelu_f((v.z-m)*r); v.w = gelu_f((v.w-m)*r);
            }
            *reinterpret_cast<float4*>(&Xs[k*128 + cq*4]) = v;
        }
        __syncthreads();
        for (int k=0;k<48;k++){
            const ull* wp = reinterpret_cast<const ull*>(&As[k*96 + tm*8]);
            ull w2[4];
            #pragma unroll
            for (int i=0;i<4;i++) w2[i] = wp[i];
            float4 x0 = *reinterpret_cast<const float4*>(&Xs[k*128 + tn*8]);
            float4 x1 = *reinterpret_cast<const float4*>(&Xs[k*128 + tn*8 + 4]);
            ull xp[8] = { pack_dup(x0.x), pack_dup(x0.y), pack_dup(x0.z), pack_dup(x0.w),
                          pack_dup(x1.x), pack_dup(x1.y), pack_dup(x1.z), pack_dup(x1.w) };
            #pragma unroll
            for (int i=0;i<4;i++)
                #pragma unroll
                for (int j=0;j<8;j++) fma2(acc2[i][j], w2[i], xp[j]);
        }
    }

    #pragma unroll
    for (int i=0;i<4;i++){
        int m = m0 + tm*8 + 2*i;
        float bi0 = bias[m], bi1 = bias[m+1];
        #pragma unroll
        for (int j=0;j<8;j++){
            int col = n0 + tn*8 + j;
            float lo, hi; unpack2(lo, hi, acc2[i][j]);
            float r0 = lo + bi0, r1 = hi + bi1;
            if (EPI==1){
                float g0 = gate[((size_t)b*96 + m  )*SVOL + col];
                float g1 = gate[((size_t)b*96 + m+1)*SVOL + col];
                r0 = g0 * (1.0f/(1.0f + __expf(-r0)));
                r1 = g1 * (1.0f/(1.0f + __expf(-r1)));
            }
            Y[((size_t)b*Mtotal + m  )*SVOL + col] = r0;
            Y[((size_t)b*Mtotal + m+1)*SVOL + col] = r1;
        }
    }
}

// ---- generic 40x40 tiled transpose (coalesced both sides), optional accumulate ----
// src index: base_s + i*S + j   (j contiguous)
// dst index: base_d + j*D + i   (i contiguous)
template<int S, int D, int SZ, int DZ, int SRCSEL, int DSTSEL, bool ACC, int CNUM>
__global__ __launch_bounds__(128) void trans40(){
    const float* src = (SRCSEL==0) ? g_qkv : (SRCSEL==1) ? g_oA : g_oB;
    float* dst = (DSTSEL==0) ? g_qkvA : (DSTSEL==1) ? g_qkvB : g_buf1;
    int z = blockIdx.x, c = blockIdx.y, b = blockIdx.z;
    size_t cc = (size_t)(b*CNUM + c)*SVOL;
    const float* sp = src + cc + (size_t)z*SZ;
    float* dp = dst + cc + (size_t)z*DZ;
    __shared__ float sm[40][41];
    for (int idx=threadIdx.x; idx<400; idx+=128){
        int i = idx/10, q = idx%10;
        float4 v = *reinterpret_cast<const float4*>(&sp[(size_t)i*S + q*4]);
        sm[i][q*4+0]=v.x; sm[i][q*4+1]=v.y; sm[i][q*4+2]=v.z; sm[i][q*4+3]=v.w;
    }
    __syncthreads();
    for (int idx=threadIdx.x; idx<400; idx+=128){
        int j = idx/10, q = idx%10;
        float4 v;
        v.x = sm[q*4+0][j]; v.y = sm[q*4+1][j]; v.z = sm[q*4+2][j]; v.w = sm[q*4+3][j];
        float* dd = &dp[(size_t)j*D + q*4];
        if (ACC){
            float4 o = *reinterpret_cast<const float4*>(dd);
            v.x+=o.x; v.y+=o.y; v.z+=o.z; v.w+=o.w;
        }
        *reinterpret_cast<float4*>(dd) = v;
    }
}

// ---- axial attention, unified contiguous lines (s0 = line*40, stride 1) ----
// SEL 0: src g_qkv  -> g_buf1 ; SEL 1: src g_qkvA -> g_oA ; SEL 2: src g_qkvB -> g_oB
template<int SEL>
__global__ __launch_bounds__(128) void attn_kernel(){
    __shared__ float qs[HD][LAX];
    __shared__ float ks[HD][LAX];
    __shared__ float vs[LAX][HD];
    __shared__ float ps[LAX][41];
    int line = blockIdx.x, head = blockIdx.y, b = blockIdx.z;
    int tid = threadIdx.x;
    int s0 = line*40;
    const float* src = (SEL==0) ? g_qkv : (SEL==1) ? g_qkvA : g_qkvB;
    float* dst = (SEL==0) ? g_buf1 : (SEL==1) ? g_oA : g_oB;
    const float* base = src + (size_t)b*288*SVOL + s0;

    // q,k: 2 tensors x 24 hd x 10 float4
    for (int idx=tid; idx<480; idx+=128){
        int t = idx/240, r = idx%240, hd = r/10, q = r%10;
        float4 v = *reinterpret_cast<const float4*>(&base[(size_t)((t*NHD+head)*HD + hd)*SVOL + q*4]);
        float* dq = (t==0) ? &qs[hd][q*4] : &ks[hd][q*4];
        *reinterpret_cast<float4*>(dq) = v;
    }
    // v: transposed store into vs[l][hd]
    for (int idx=tid; idx<240; idx+=128){
        int hd = idx/10, q = idx%10;
        float4 v = *reinterpret_cast<const float4*>(&base[(size_t)((2*NHD+head)*HD + hd)*SVOL + q*4]);
        vs[q*4+0][hd]=v.x; vs[q*4+1][hd]=v.y; vs[q*4+2][hd]=v.z; vs[q*4+3][hd]=v.w;
    }
    __syncthreads();

    const float scale = 0.2041241452319315f;  // 24^-0.5
    for (int idx=tid; idx<400; idx+=128){
        int i = idx/10, j0 = (idx%10)*4;
        float a0=0.f,a1=0.f,a2=0.f,a3=0.f;
        #pragma unroll
        for (int hd=0; hd<HD; hd++){
            float qv = qs[hd][i];
            float4 kv = *reinterpret_cast<const float4*>(&ks[hd][j0]);
            a0 = fmaf(qv,kv.x,a0); a1 = fmaf(qv,kv.y,a1);
            a2 = fmaf(qv,kv.z,a2); a3 = fmaf(qv,kv.w,a3);
        }
        ps[i][j0+0]=a0*scale; ps[i][j0+1]=a1*scale;
        ps[i][j0+2]=a2*scale; ps[i][j0+3]=a3*scale;
    }
    __syncthreads();
    if (tid < 40){
        float mx = -1e30f;
        for (int j=0;j<40;j++) mx = fmaxf(mx, ps[tid][j]);
        float sum = 0.f;
        for (int j=0;j<40;j++){ float e = __expf(ps[tid][j]-mx); ps[tid][j]=e; sum+=e; }
        float inv = 1.0f/sum;
        for (int j=0;j<40;j++) ps[tid][j]*=inv;
    }
    __syncthreads();
    // PV with coalesced float4 output: thread -> (hd, quad of i)
    for (int idx=tid; idx<240; idx+=128){
        int hd = idx/10, i0 = (idx%10)*4;
        float a0=0.f,a1=0.f,a2=0.f,a3=0.f;
        #pragma unroll
        for (int j=0;j<40;j++){
            float vv = vs[j][hd];
            a0 = fmaf(ps[i0+0][j], vv, a0);
            a1 = fmaf(ps[i0+1][j], vv, a1);
            a2 = fmaf(ps[i0+2][j], vv, a2);
            a3 = fmaf(ps[i0+3][j], vv, a3);
        }
        float4 r; r.x=a0; r.y=a1; r.z=a2; r.w=a3;
        *reinterpret_cast<float4*>(&dst[(size_t)((b*CC) + head*HD + hd)*SVOL + s0 + i0]) = r;
    }
}

extern "C" void kernel_launch(void* const* d_in, const int* in_sizes, int n_in,
                              void* d_out, int out_size){
    const float* x     = (const float*)d_in[0];
    const float* pe    = (const float*)d_in[1];
    const float* qkv_w = (const float*)d_in[2];
    const float* qkv_b = (const float*)d_in[3];
    const float* lp1_w = (const float*)d_in[4];
    const float* lp1_b = (const float*)d_in[5];
    const float* lp2_w = (const float*)d_in[6];
    const float* lp2_b = (const float*)d_in[7];
    const float* mod1_w= (const float*)d_in[8];
    const float* mod1_b= (const float*)d_in[9];
    const float* mod2_w= (const float*)d_in[10];
    const float* mod2_b= (const float*)d_in[11];
    // d_in[12..16] (pa_w, pa_b, R6_d/h/w) are mathematically dead:
    //   pos_attn adds a per-row constant under softmax; R is orthogonal so q.k is invariant.
    const float* proj_w= (const float*)d_in[17];
    const float* proj_b= (const float*)d_in[18];
    float* out = (float*)d_out;

    prep_w27 <<<(27*96*96+255)/256, 256>>>(lp1_w);
    prep_pad <<<(int)(((size_t)BB*96*42*42*44 + 255)/256), 256>>>(pe);
    prep_fold<<<(96*96+255)/256,    256>>>(mod1_w, lp2_w, lp2_b, mod1_b);
    prep_trans<<<(96*288+255)/256,  256>>>(mod2_w, qkv_w, proj_w);

    // t1 = conv3(pos_emb) -> buf0
    conv3_kernel<<<dim3(20,40,BB), 96>>>(lp1_b);
    in_stats<0,1><<<BB*CC, 256>>>();
    // u = Wc @ gelu(IN(t1)) + bc -> buf1
    gemm_kernel<1,0,0,0,1,1,1><<<dim3(500,1,BB), 192>>>(96, nullptr, nullptr, nullptr);
    in_stats<1,2><<<BB*CC, 256>>>();
    // xm = x * sigmoid(mod2 @ gelu(IN(u)) + b) -> buf0 (t1 dead)
    gemm_kernel<1,1,1,1,0,2,0><<<dim3(500,1,BB), 192>>>(96, nullptr, mod2_b, x);
    // qkv = qkv_w @ xm + qkv_b
    gemm_kernel<0,0,2,0,2,0,0><<<dim3(500,3,BB), 192>>>(288, nullptr, qkv_b, nullptr);

    // build axis-contiguous qkv copies
    trans40<40,  40,1600,1600, 0,0,false,288><<<dim3(40,288,BB), 128>>>();  // std -> A (h-fast)
    trans40<1600,40,  40,1600, 0,1,false,288><<<dim3(40,288,BB), 128>>>();  // std -> B (d-fast)

    // axial attention, all contiguous
    attn_kernel<0><<<dim3(1600,NHD,BB), 128>>>();   // -> buf1
    attn_kernel<1><<<dim3(1600,NHD,BB), 128>>>();   // -> oA
    attn_kernel<2><<<dim3(1600,NHD,BB), 128>>>();   // -> oB

    // fold strided-axis outputs back into buf1 (transpose + accumulate)
    trans40<40,  40,1600,1600, 1,2,true, 96><<<dim3(40,96,BB), 128>>>();    // oA -> buf1
    trans40<40,1600,1600,  40, 2,2,true, 96><<<dim3(40,96,BB), 128>>>();    // oB -> buf1

    // out = proj @ o + proj_b
    gemm_kernel<0,0,3,1,3,0,0><<<dim3(500,1,BB), 192>>>(96, out, proj_b, nullptr);
}

// round 14
// speedup vs baseline: 1.8378x; 1.2918x over previous
#include <cuda_runtime.h>
#include <math.h>

#define SVOL 64000
#define BB   2
#define CC   96
#define NHD  4
#define HD   24
#define LAX  40
#define XPITCH 20
#define WPITCH 104

typedef unsigned long long ull;
typedef unsigned int uint32;

// ---- scratch: __device__ globals (no allocation anywhere) ----
__device__ float g_buf0[BB*CC*SVOL];   // conv out t1 -> x*mod
__device__ float g_buf1[BB*CC*SVOL];   // u -> attention accumulator
__device__ float g_qkv [BB*288*SVOL];  // std layout: d*1600 + h*40 + w
__device__ float g_qkvA[BB*288*SVOL];  // h-fastest
__device__ float g_qkvB[BB*288*SVOL];  // d-fastest
__device__ float g_oA  [BB*CC*SVOL];
__device__ float g_oB  [BB*CC*SVOL];
__device__ float g_pad [(size_t)BB*96*42*42*44];   // padded pos_emb, tf32-rounded
__device__ float g_mu1[BB*CC], g_rs1[BB*CC], g_mu2[BB*CC], g_rs2[BB*CC];
__device__ float g_W27  [27*96*96];    // [tap][ic][oc], tf32-rounded
__device__ float g_WcT  [96*96];
__device__ float g_bc   [96];
__device__ float g_mod2T[96*96];
__device__ float g_qkvT [96*288];
__device__ float g_projT[96*96];

__device__ __forceinline__ float gelu_f(float v){
    return 0.5f*v*(1.0f + erff(v*0.70710678118654752f));
}
__device__ __forceinline__ ull pack_dup(float x){
    ull r; asm("mov.b64 %0, {%1, %1};" : "=l"(r) : "f"(x)); return r;
}
__device__ __forceinline__ void fma2(ull& d, ull a, ull b){
    asm("fma.rn.f32x2 %0, %1, %2, %0;" : "+l"(d) : "l"(a), "l"(b));
}
__device__ __forceinline__ void unpack2(float& lo, float& hi, ull v){
    asm("mov.b64 {%0, %1}, %2;" : "=f"(lo), "=f"(hi) : "l"(v));
}
__device__ __forceinline__ float to_tf32(float v){
    uint32 u; asm("cvt.rna.tf32.f32 %0, %1;" : "=r"(u) : "f"(v));
    return __uint_as_float(u);
}

// ---- weight / input prep ----
__global__ void prep_w27(const float* __restrict__ lp1_w){
    int tid = blockIdx.x*blockDim.x + threadIdx.x;
    if (tid < 27*96*96){
        int t = tid/(96*96); int r = tid%(96*96); int ic = r/96; int oc = r%96;
        g_W27[tid] = to_tf32(lp1_w[(oc*96+ic)*27 + t]);
    }
}
__global__ void prep_pad(const float* __restrict__ pe){
    size_t idx = (size_t)blockIdx.x*256 + threadIdx.x;
    if (idx >= (size_t)BB*96*42*42*44) return;
    int pw = (int)(idx % 44); size_t r = idx/44;
    int ph = (int)(r % 42); r /= 42;
    int pd = (int)(r % 42); r /= 42;
    int c  = (int)(r % 96); int b = (int)(r/96);
    int d = (pd+39)%40, h = (ph+39)%40, w = (pw+39)%40;
    g_pad[idx] = to_tf32(pe[(size_t)(b*96+c)*SVOL + d*1600 + h*40 + w]);
}
__global__ void prep_fold(const float* __restrict__ mod1_w, const float* __restrict__ lp2_w,
                          const float* __restrict__ lp2_b, const float* __restrict__ mod1_b){
    int tid = blockIdx.x*blockDim.x + threadIdx.x;
    if (tid < 96*96){
        int k = tid/96, m = tid%96;
        float s = 0.f;
        for (int o = 0; o < 96; o++) s += mod1_w[m*96+o]*lp2_w[o*96+k];
        g_WcT[k*96+m] = s;
        if (k == 0){
            float b2 = 0.f;
            for (int o = 0; o < 96; o++) b2 += mod1_w[m*96+o]*lp2_b[o];
            g_bc[m] = b2 + mod1_b[m];
        }
    }
}
__global__ void prep_trans(const float* __restrict__ mod2_w, const float* __restrict__ qkv_w,
                           const float* __restrict__ proj_w){
    int tid = blockIdx.x*blockDim.x + threadIdx.x;
    if (tid < 96*96){
        int k = tid/96, m = tid%96;
        g_mod2T[k*96+m] = mod2_w[m*96+k];
        g_projT[k*96+m] = proj_w[m*96+k];
    }
    if (tid < 96*288){
        int k = tid/288, m = tid%288;
        g_qkvT[k*288+m] = qkv_w[m*96+k];
    }
}

// ---- conv3x3x3 circular as implicit GEMM on mma.sync tf32 ----
// block: 96 oc x 160 cols (4 h-rows x 40 w) at fixed (b,d). 6 warps (16 oc each).
// smem: Xs[6 rows][44 cols][ic pitch 20] + Ws[3 dx][16 ic][oc pitch 104]
__global__ __launch_bounds__(192) void conv3_mma(const float* __restrict__ lp1_b){
    __shared__ float Xs[6*44*XPITCH];     // 5280 floats
    __shared__ float Ws[3*16*WPITCH];     // 4992 floats
    int b = blockIdx.z, d = blockIdx.y, h0 = blockIdx.x*4;
    int tid = threadIdx.x;
    int warp = tid/32, lane = tid%32;
    int gid = lane>>2, tig = lane&3;
    int oc0 = warp*16;

    float acc[20][4];
    #pragma unroll
    for (int j=0;j<20;j++){ acc[j][0]=0.f; acc[j][1]=0.f; acc[j][2]=0.f; acc[j][3]=0.f; }

    // B-load base offsets per n-tile (n = j*8 + gid)
    int xoff[20];
    #pragma unroll
    for (int j=0;j<20;j++){
        int n = j*8 + gid;
        xoff[j] = ((n/40)*44 + (n%40))*XPITCH;
    }

    for (int dz=0; dz<3; dz++){
        int pd = d + dz;
        for (int kc=0; kc<6; kc++){
            __syncthreads();
            // stage Xs: 16 ic x 6 rows x 44 cols -> [row][col][ic]
            for (int idx=tid; idx<1056; idx+=192){
                int r = idx/11, q = idx%11;
                int ic = r/6, rr = r%6;
                float4 v = *reinterpret_cast<const float4*>(
                    &g_pad[(((size_t)(b*96 + kc*16 + ic)*42 + pd)*42 + (h0+rr))*44 + q*4]);
                float* dp = &Xs[(rr*44 + q*4)*XPITCH + ic];
                dp[0]=v.x; dp[XPITCH]=v.y; dp[2*XPITCH]=v.z; dp[3*XPITCH]=v.w;
            }
            for (int dy=0; dy<3; dy++){
                int t0 = (dz*3+dy)*3;
                __syncthreads();
                // stage Ws: [dx][ic][oc], oc pitch 104
                for (int idx=tid; idx<1152; idx+=192){
                    int dx = idx/384, r2 = idx%384;
                    int ic = r2/24, q = r2%24;
                    float4 v = *reinterpret_cast<const float4*>(
                        &g_W27[(size_t)(t0+dx)*9216 + (kc*16+ic)*96 + q*4]);
                    *reinterpret_cast<float4*>(&Ws[(dx*16+ic)*WPITCH + q*4]) = v;
                }
                __syncthreads();
                #pragma unroll
                for (int dx=0; dx<3; dx++){
                    #pragma unroll
                    for (int ks=0; ks<2; ks++){
                        const float* wb = &Ws[(dx*16 + ks*8 + tig)*WPITCH + oc0 + gid];
                        uint32 a0 = __float_as_uint(wb[0]);
                        uint32 a1 = __float_as_uint(wb[8]);
                        uint32 a2 = __float_as_uint(wb[4*WPITCH]);
                        uint32 a3 = __float_as_uint(wb[4*WPITCH+8]);
                        int boff = (dy*44 + dx)*XPITCH + ks*8 + tig;
                        #pragma unroll
                        for (int j=0;j<20;j++){
                            uint32 b0 = __float_as_uint(Xs[xoff[j] + boff]);
                            uint32 b1 = __float_as_uint(Xs[xoff[j] + boff + 4]);
                            asm volatile(
                                "mma.sync.aligned.m16n8k8.row.col.f32.tf32.tf32.f32 "
                                "{%0,%1,%2,%3}, {%4,%5,%6,%7}, {%8,%9}, {%0,%1,%2,%3};"
                                : "+f"(acc[j][0]), "+f"(acc[j][1]), "+f"(acc[j][2]), "+f"(acc[j][3])
                                : "r"(a0), "r"(a1), "r"(a2), "r"(a3), "r"(b0), "r"(b1));
                        }
                    }
                }
            }
        }
    }

    // write out: c0,c1 -> oc0+gid, cols n..n+1 ; c2,c3 -> oc0+gid+8
    size_t obase = (size_t)b*CC*SVOL + d*1600 + h0*40;
    int oca = oc0 + gid, ocb = oca + 8;
    float ba = lp1_b[oca], bb2 = lp1_b[ocb];
    #pragma unroll
    for (int j=0;j<20;j++){
        int n = j*8 + 2*tig;
        int g = n/40, wn = n%40;
        size_t o1 = obase + (size_t)oca*SVOL + g*40 + wn;
        size_t o2 = obase + (size_t)ocb*SVOL + g*40 + wn;
        float2 v1; v1.x = acc[j][0]+ba;  v1.y = acc[j][1]+ba;
        float2 v2; v2.x = acc[j][2]+bb2; v2.y = acc[j][3]+bb2;
        *reinterpret_cast<float2*>(&g_buf0[o1]) = v1;
        *reinterpret_cast<float2*>(&g_buf0[o2]) = v2;
    }
}

// ---- per-(b,c) instance-norm stats ----
template<int SRC, int SET>
__global__ __launch_bounds__(256) void in_stats(){
    const float* src = (SRC==0) ? g_buf0 : g_buf1;
    float* mu = (SET==1) ? g_mu1 : g_mu2;
    float* rs = (SET==1) ? g_rs1 : g_rs2;
    int bc = blockIdx.x;
    const float* p = src + (size_t)bc*SVOL;
    float s=0.f, s2=0.f;
    for (int i=threadIdx.x; i<SVOL/4; i+=256){
        float4 v = reinterpret_cast<const float4*>(p)[i];
        s += v.x+v.y+v.z+v.w;
        s2 = fmaf(v.x,v.x,s2); s2 = fmaf(v.y,v.y,s2);
        s2 = fmaf(v.z,v.z,s2); s2 = fmaf(v.w,v.w,s2);
    }
    __shared__ float r1[256], r2[256];
    r1[threadIdx.x]=s; r2[threadIdx.x]=s2;
    __syncthreads();
    for (int off=128; off>0; off>>=1){
        if (threadIdx.x<off){ r1[threadIdx.x]+=r1[threadIdx.x+off]; r2[threadIdx.x]+=r2[threadIdx.x+off]; }
        __syncthreads();
    }
    if (threadIdx.x==0){
        float m = r1[0]*(1.0f/SVOL);
        float var = r2[0]*(1.0f/SVOL) - m*m;
        mu[bc]=m; rs[bc]=rsqrtf(var + 1e-5f);
    }
}

// ---- fused 1x1-conv GEMM, f32x2 packed over m pairs ----
template<int PRO, int EPI, int AW, int SRC, int DST, int SET, int BIASG>
__global__ __launch_bounds__(192) void gemm_kernel(
    int Mtotal, float* __restrict__ extY,
    const float* __restrict__ bias_ext,
    const float* __restrict__ gate)
{
    __shared__ float As[48*96];
    __shared__ float Xs[48*128];
    const float* AT = (AW==0) ? g_WcT : (AW==1) ? g_mod2T : (AW==2) ? g_qkvT : g_projT;
    const float* X  = (SRC==0) ? g_buf0 : g_buf1;
    float* Y = (DST==0) ? g_buf0 : (DST==1) ? g_buf1 : (DST==2) ? g_qkv : extY;
    const float* bias = (BIASG==1) ? g_bc : bias_ext;
    const float* mu = (SET==1) ? g_mu1 : g_mu2;
    const float* rs = (SET==1) ? g_rs1 : g_rs2;

    int b = blockIdx.z, m0 = blockIdx.y*96, n0 = blockIdx.x*128;
    int tid = threadIdx.x, tm = tid/16, tn = tid%16;
    const float* xb = X + (size_t)b*96*SVOL + n0;

    ull acc2[4][8];
    #pragma unroll
    for (int i=0;i<4;i++)
        #pragma unroll
        for (int j=0;j<8;j++) acc2[i][j]=0ULL;

    for (int kc=0; kc<2; kc++){
        __syncthreads();
        for (int idx=tid; idx<1152; idx+=192){
            int k = idx/24, mq = idx%24;
            *reinterpret_cast<float4*>(&As[k*96 + mq*4]) =
                *reinterpret_cast<const float4*>(&AT[(kc*48+k)*Mtotal + m0 + mq*4]);
        }
        for (int idx=tid; idx<1536; idx+=192){
            int k = idx/32, cq = idx%32;
            int kg = kc*48 + k;
            float4 v = *reinterpret_cast<const float4*>(&xb[(size_t)kg*SVOL + cq*4]);
            if (PRO==1){
                float m = mu[b*96+kg], r = rs[b*96+kg];
                v.x = gelu_f((v.x-m)*r); v.y = gelu_f((v.y-m)*r);
                v.z = gelu_f((v.z-m)*r); v.w = gelu_f((v.w-m)*r);
            }
            *reinterpret_cast<float4*>(&Xs[k*128 + cq*4]) = v;
        }
        __syncthreads();
        for (int k=0;k<48;k++){
            const ull* wp = reinterpret_cast<const ull*>(&As[k*96 + tm*8]);
            ull w2[4];
            #pragma unroll
            for (int i=0;i<4;i++) w2[i] = wp[i];
            float4 x0 = *reinterpret_cast<const float4*>(&Xs[k*128 + tn*8]);
            float4 x1 = *reinterpret_cast<const float4*>(&Xs[k*128 + tn*8 + 4]);
            ull xp[8] = { pack_dup(x0.x), pack_dup(x0.y), pack_dup(x0.z), pack_dup(x0.w),
                          pack_dup(x1.x), pack_dup(x1.y), pack_dup(x1.z), pack_dup(x1.w) };
            #pragma unroll
            for (int i=0;i<4;i++)
                #pragma unroll
                for (int j=0;j<8;j++) fma2(acc2[i][j], w2[i], xp[j]);
        }
    }

    #pragma unroll
    for (int i=0;i<4;i++){
        int m = m0 + tm*8 + 2*i;
        float bi0 = bias[m], bi1 = bias[m+1];
        #pragma unroll
        for (int j=0;j<8;j++){
            int col = n0 + tn*8 + j;
            float lo, hi; unpack2(lo, hi, acc2[i][j]);
            float r0 = lo + bi0, r1 = hi + bi1;
            if (EPI==1){
                float g0 = gate[((size_t)b*96 + m  )*SVOL + col];
                float g1 = gate[((size_t)b*96 + m+1)*SVOL + col];
                r0 = g0 * (1.0f/(1.0f + __expf(-r0)));
                r1 = g1 * (1.0f/(1.0f + __expf(-r1)));
            }
            Y[((size_t)b*Mtotal + m  )*SVOL + col] = r0;
            Y[((size_t)b*Mtotal + m+1)*SVOL + col] = r1;
        }
    }
}

// ---- generic 40x40 tiled transpose, optional accumulate ----
template<int S, int D, int SZ, int DZ, int SRCSEL, int DSTSEL, bool ACC, int CNUM>
__global__ __launch_bounds__(128) void trans40(){
    const float* src = (SRCSEL==0) ? g_qkv : (SRCSEL==1) ? g_oA : g_oB;
    float* dst = (DSTSEL==0) ? g_qkvA : (DSTSEL==1) ? g_qkvB : g_buf1;
    int z = blockIdx.x, c = blockIdx.y, b = blockIdx.z;
    size_t cc = (size_t)(b*CNUM + c)*SVOL;
    const float* sp = src + cc + (size_t)z*SZ;
    float* dp = dst + cc + (size_t)z*DZ;
    __shared__ float sm[40][41];
    for (int idx=threadIdx.x; idx<400; idx+=128){
        int i = idx/10, q = idx%10;
        float4 v = *reinterpret_cast<const float4*>(&sp[(size_t)i*S + q*4]);
        sm[i][q*4+0]=v.x; sm[i][q*4+1]=v.y; sm[i][q*4+2]=v.z; sm[i][q*4+3]=v.w;
    }
    __syncthreads();
    for (int idx=threadIdx.x; idx<400; idx+=128){
        int j = idx/10, q = idx%10;
        float4 v;
        v.x = sm[q*4+0][j]; v.y = sm[q*4+1][j]; v.z = sm[q*4+2][j]; v.w = sm[q*4+3][j];
        float* dd = &dp[(size_t)j*D + q*4];
        if (ACC){
            float4 o = *reinterpret_cast<const float4*>(dd);
            v.x+=o.x; v.y+=o.y; v.z+=o.z; v.w+=o.w;
        }
        *reinterpret_cast<float4*>(dd) = v;
    }
}

// ---- axial attention, contiguous lines ----
template<int SEL>
__global__ __launch_bounds__(128) void attn_kernel(){
    __shared__ float qs[HD][LAX];
    __shared__ float ks[HD][LAX];
    __shared__ float vs[LAX][HD];
    __shared__ float ps[LAX][41];
    int line = blockIdx.x, head = blockIdx.y, b = blockIdx.z;
    int tid = threadIdx.x;
    int s0 = line*40;
    const float* src = (SEL==0) ? g_qkv : (SEL==1) ? g_qkvA : g_qkvB;
    float* dst = (SEL==0) ? g_buf1 : (SEL==1) ? g_oA : g_oB;
    const float* base = src + (size_t)b*288*SVOL + s0;

    for (int idx=tid; idx<480; idx+=128){
        int t = idx/240, r = idx%240, hd = r/10, q = r%10;
        float4 v = *reinterpret_cast<const float4*>(&base[(size_t)((t*NHD+head)*HD + hd)*SVOL + q*4]);
        float* dq = (t==0) ? &qs[hd][q*4] : &ks[hd][q*4];
        *reinterpret_cast<float4*>(dq) = v;
    }
    for (int idx=tid; idx<240; idx+=128){
        int hd = idx/10, q = idx%10;
        float4 v = *reinterpret_cast<const float4*>(&base[(size_t)((2*NHD+head)*HD + hd)*SVOL + q*4]);
        vs[q*4+0][hd]=v.x; vs[q*4+1][hd]=v.y; vs[q*4+2][hd]=v.z; vs[q*4+3][hd]=v.w;
    }
    __syncthreads();

    const float scale = 0.2041241452319315f;
    for (int idx=tid; idx<400; idx+=128){
        int i = idx/10, j0 = (idx%10)*4;
        float a0=0.f,a1=0.f,a2=0.f,a3=0.f;
        #pragma unroll
        for (int hd=0; hd<HD; hd++){
            float qv = qs[hd][i];
            float4 kv = *reinterpret_cast<const float4*>(&ks[hd][j0]);
            a0 = fmaf(qv,kv.x,a0); a1 = fmaf(qv,kv.y,a1);
            a2 = fmaf(qv,kv.z,a2); a3 = fmaf(qv,kv.w,a3);
        }
        ps[i][j0+0]=a0*scale; ps[i][j0+1]=a1*scale;
        ps[i][j0+2]=a2*scale; ps[i][j0+3]=a3*scale;
    }
    __syncthreads();
    if (tid < 40){
        float mx = -1e30f;
        for (int j=0;j<40;j++) mx = fmaxf(mx, ps[tid][j]);
        float sum = 0.f;
        for (int j=0;j<40;j++){ float e = __expf(ps[tid][j]-mx); ps[tid][j]=e; sum+=e; }
        float inv = 1.0f/sum;
        for (int j=0;j<40;j++) ps[tid][j]*=inv;
    }
    __syncthreads();
    for (int idx=tid; idx<240; idx+=128){
        int hd = idx/10, i0 = (idx%10)*4;
        float a0=0.f,a1=0.f,a2=0.f,a3=0.f;
        #pragma unroll
        for (int j=0;j<40;j++){
            float vv = vs[j][hd];
            a0 = fmaf(ps[i0+0][j], vv, a0);
            a1 = fmaf(ps[i0+1][j], vv, a1);
            a2 = fmaf(ps[i0+2][j], vv, a2);
            a3 = fmaf(ps[i0+3][j], vv, a3);
        }
        float4 r; r.x=a0; r.y=a1; r.z=a2; r.w=a3;
        *reinterpret_cast<float4*>(&dst[(size_t)((b*CC) + head*HD + hd)*SVOL + s0 + i0]) = r;
    }
}

extern "C" void kernel_launch(void* const* d_in, const int* in_sizes, int n_in,
                              void* d_out, int out_size){
    const float* x     = (const float*)d_in[0];
    const float* pe    = (const float*)d_in[1];
    const float* qkv_w = (const float*)d_in[2];
    const float* qkv_b = (const float*)d_in[3];
    const float* lp1_w = (const float*)d_in[4];
    const float* lp1_b = (const float*)d_in[5];
    const float* lp2_w = (const float*)d_in[6];
    const float* lp2_b = (const float*)d_in[7];
    const float* mod1_w= (const float*)d_in[8];
    const float* mod1_b= (const float*)d_in[9];
    const float* mod2_w= (const float*)d_in[10];
    const float* mod2_b= (const float*)d_in[11];
    // d_in[12..16] (pa_w, pa_b, R6_d/h/w) are mathematically dead:
    //   pos_attn adds a per-row constant under softmax; R is orthogonal so q.k is invariant.
    const float* proj_w= (const float*)d_in[17];
    const float* proj_b= (const float*)d_in[18];
    float* out = (float*)d_out;

    prep_w27 <<<(27*96*96+255)/256, 256>>>(lp1_w);
    prep_pad <<<(int)(((size_t)BB*96*42*42*44 + 255)/256), 256>>>(pe);
    prep_fold<<<(96*96+255)/256,    256>>>(mod1_w, lp2_w, lp2_b, mod1_b);
    prep_trans<<<(96*288+255)/256,  256>>>(mod2_w, qkv_w, proj_w);

    // t1 = conv3(pos_emb) -> buf0  (tensor-core tf32 implicit GEMM)
    conv3_mma<<<dim3(10,40,BB), 192>>>(lp1_b);
    in_stats<0,1><<<BB*CC, 256>>>();
    // u = Wc @ gelu(IN(t1)) + bc -> buf1
    gemm_kernel<1,0,0,0,1,1,1><<<dim3(500,1,BB), 192>>>(96, nullptr, nullptr, nullptr);
    in_stats<1,2><<<BB*CC, 256>>>();
    // xm = x * sigmoid(mod2 @ gelu(IN(u)) + b) -> buf0 (t1 dead)
    gemm_kernel<1,1,1,1,0,2,0><<<dim3(500,1,BB), 192>>>(96, nullptr, mod2_b, x);
    // qkv = qkv_w @ xm + qkv_b
    gemm_kernel<0,0,2,0,2,0,0><<<dim3(500,3,BB), 192>>>(288, nullptr, qkv_b, nullptr);

    // build axis-contiguous qkv copies
    trans40<40,  40,1600,1600, 0,0,false,288><<<dim3(40,288,BB), 128>>>();
    trans40<1600,40,  40,1600, 0,1,false,288><<<dim3(40,288,BB), 128>>>();

    // axial attention, all contiguous
    attn_kernel<0><<<dim3(1600,NHD,BB), 128>>>();
    attn_kernel<1><<<dim3(1600,NHD,BB), 128>>>();
    attn_kernel<2><<<dim3(1600,NHD,BB), 128>>>();

    // fold strided-axis outputs back into buf1
    trans40<40,  40,1600,1600, 1,2,true, 96><<<dim3(40,96,BB), 128>>>();
    trans40<40,1600,1600,  40, 2,2,true, 96><<<dim3(40,96,BB), 128>>>();

    // out = proj @ o + proj_b
    gemm_kernel<0,0,3,1,3,0,0><<<dim3(500,1,BB), 192>>>(96, out, proj_b, nullptr);
}